// round 1
// baseline (speedup 1.0000x reference)
#include <cuda_runtime.h>
#include <cuda_bf16.h>

// ---------------------------------------------------------------------------
// SimpleGAT on GB300 (sm_103a)
// Pipeline:
//   K1: h = x @ W_lin^T  (+ fused s_node = h@att[:H], d_node = h@att[H:])
//   K0: zero denom / agg
//   K2: per-edge  w = exp(leaky_relu(s[src]+d[dst]))  (global-max skipped:
//       it cancels in alpha up to the 1e-9 eps, rel effect < 1e-6),
//       denom[dst] += w  (scalar REDG)
//   K3: per-(edge, 16B-chunk)  agg[dst] += h[src] * (w/denom[dst])
//       via red.global.add.v4.f32
//   K4: out = relu(agg) @ W_out^T + b_out
// ---------------------------------------------------------------------------

#define N_MAX 100000
#define E_MAX 1600000

__device__ float g_h[N_MAX * 64];
__device__ float g_s[N_MAX];
__device__ float g_d[N_MAX];
__device__ float g_w[E_MAX];
__device__ float g_denom[N_MAX];
__device__ float g_agg[N_MAX * 64];

// ------------------------- K1: input GEMM + att proj -----------------------
// Tile 64 rows x 64 cols, K=128 in chunks of 16. 256 threads, 4x4 microtile.
__global__ __launch_bounds__(256) void gemm_h_kernel(
    const float* __restrict__ x, const float* __restrict__ Wlin,
    const float* __restrict__ att, int N)
{
    __shared__ float As[16][64];   // As[k][row]
    __shared__ float Bs[16][64];   // Bs[k][col]  (= Wlin[col][k])

    const int tid = threadIdx.x;
    const int tc  = tid & 15;      // col group (cols tc*4 .. tc*4+3)
    const int tr  = tid >> 4;      // row group (rows tr*4 .. tr*4+3)
    const int row0 = blockIdx.x * 64;

    const int lrow = tid >> 2;     // loader: 0..63
    const int lq   = tid & 3;      // loader quad: 0..3

    float acc[4][4];
#pragma unroll
    for (int i = 0; i < 4; i++)
#pragma unroll
        for (int j = 0; j < 4; j++) acc[i][j] = 0.f;

    for (int k0 = 0; k0 < 128; k0 += 16) {
        const int grow = row0 + lrow;
        float4 xa = make_float4(0.f, 0.f, 0.f, 0.f);
        if (grow < N)
            xa = *(const float4*)&x[grow * 128 + k0 + lq * 4];
        const float4 wa = *(const float4*)&Wlin[lrow * 128 + k0 + lq * 4];

        __syncthreads();
        As[lq * 4 + 0][lrow] = xa.x;
        As[lq * 4 + 1][lrow] = xa.y;
        As[lq * 4 + 2][lrow] = xa.z;
        As[lq * 4 + 3][lrow] = xa.w;
        Bs[lq * 4 + 0][lrow] = wa.x;
        Bs[lq * 4 + 1][lrow] = wa.y;
        Bs[lq * 4 + 2][lrow] = wa.z;
        Bs[lq * 4 + 3][lrow] = wa.w;
        __syncthreads();

#pragma unroll
        for (int kk = 0; kk < 16; kk++) {
            const float4 a = *(const float4*)&As[kk][tr * 4];
            const float4 b = *(const float4*)&Bs[kk][tc * 4];
            acc[0][0] += a.x * b.x; acc[0][1] += a.x * b.y;
            acc[0][2] += a.x * b.z; acc[0][3] += a.x * b.w;
            acc[1][0] += a.y * b.x; acc[1][1] += a.y * b.y;
            acc[1][2] += a.y * b.z; acc[1][3] += a.y * b.w;
            acc[2][0] += a.z * b.x; acc[2][1] += a.z * b.y;
            acc[2][2] += a.z * b.z; acc[2][3] += a.z * b.w;
            acc[3][0] += a.w * b.x; acc[3][1] += a.w * b.y;
            acc[3][2] += a.w * b.z; acc[3][3] += a.w * b.w;
        }
    }

    // att slices for this thread's 4 columns
    float attS[4], attD[4];
#pragma unroll
    for (int j = 0; j < 4; j++) {
        attS[j] = att[tc * 4 + j];
        attD[j] = att[64 + tc * 4 + j];
    }

#pragma unroll
    for (int i = 0; i < 4; i++) {
        const int r = row0 + tr * 4 + i;
        if (r < N) {
            float4 hv = make_float4(acc[i][0], acc[i][1], acc[i][2], acc[i][3]);
            *(float4*)&g_h[r * 64 + tc * 4] = hv;
        }
        float sp = acc[i][0] * attS[0] + acc[i][1] * attS[1] +
                   acc[i][2] * attS[2] + acc[i][3] * attS[3];
        float dp = acc[i][0] * attD[0] + acc[i][1] * attD[1] +
                   acc[i][2] * attD[2] + acc[i][3] * attD[3];
        // reduce over the 16 tc lanes (xor masks 1..8 stay within the half-warp)
#pragma unroll
        for (int m = 8; m >= 1; m >>= 1) {
            sp += __shfl_xor_sync(0xffffffffu, sp, m);
            dp += __shfl_xor_sync(0xffffffffu, dp, m);
        }
        if (tc == 0 && r < N) {
            g_s[r] = sp;
            g_d[r] = dp;
        }
    }
}

// ------------------------- K0: zero scratch --------------------------------
__global__ void zero_all(int N)
{
    const int i = blockIdx.x * blockDim.x + threadIdx.x;
    if (i < N) g_denom[i] = 0.f;
    if (i < N * 64) g_agg[i] = 0.f;
}

// ------------------------- K2: edge weights + denom ------------------------
__global__ __launch_bounds__(256) void edge1_kernel(const int* __restrict__ ei, int E)
{
    const int t = blockIdx.x * blockDim.x + threadIdx.x;
    if (t >= E) return;
    const int src = ei[t];
    const int dst = ei[E + t];
    float e = g_s[src] + g_d[dst];
    e = (e > 0.f) ? e : 0.2f * e;        // leaky_relu, slope 0.2
    const float wv = __expf(e);
    g_w[t] = wv;
    atomicAdd(&g_denom[dst], wv);
}

// ------------------------- K3: weighted scatter-add ------------------------
// 16 threads per edge, each owns one float4 of the 64-wide h row.
__global__ __launch_bounds__(256) void edge2_kernel(const int* __restrict__ ei, int E)
{
    const unsigned t = blockIdx.x * blockDim.x + threadIdx.x;
    const int edge = (int)(t >> 4);
    if (edge >= E) return;
    const int part = (int)(t & 15);
    const int src = ei[edge];
    const int dst = ei[E + edge];
    const float alpha = g_w[edge] / (g_denom[dst] + 1e-9f);
    const float4 hv = ((const float4*)g_h)[src * 16 + part];
    float* addr = &g_agg[dst * 64 + part * 4];
    asm volatile("red.global.add.v4.f32 [%0], {%1, %2, %3, %4};"
                 :: "l"(addr),
                    "f"(hv.x * alpha), "f"(hv.y * alpha),
                    "f"(hv.z * alpha), "f"(hv.w * alpha)
                 : "memory");
}

// ------------------------- K4: output GEMM ---------------------------------
// out = relu(agg) @ W_out^T + b_out.  Same tiling as K1, K=64.
__global__ __launch_bounds__(256) void gemm_out_kernel(
    const float* __restrict__ Wout, const float* __restrict__ bout,
    float* __restrict__ out, int N)
{
    __shared__ float As[16][64];   // As[k][row] = relu(agg[row][k])
    __shared__ float Bs[16][64];   // Bs[k][o]   = Wout[o][k]

    const int tid = threadIdx.x;
    const int tc  = tid & 15;
    const int tr  = tid >> 4;
    const int row0 = blockIdx.x * 64;

    const int lrow = tid >> 2;
    const int lq   = tid & 3;

    float acc[4][4];
#pragma unroll
    for (int i = 0; i < 4; i++)
#pragma unroll
        for (int j = 0; j < 4; j++) acc[i][j] = 0.f;

    for (int k0 = 0; k0 < 64; k0 += 16) {
        const int grow = row0 + lrow;
        float4 aa = make_float4(0.f, 0.f, 0.f, 0.f);
        if (grow < N)
            aa = *(const float4*)&g_agg[grow * 64 + k0 + lq * 4];
        aa.x = fmaxf(aa.x, 0.f); aa.y = fmaxf(aa.y, 0.f);
        aa.z = fmaxf(aa.z, 0.f); aa.w = fmaxf(aa.w, 0.f);
        const float4 wa = *(const float4*)&Wout[lrow * 64 + k0 + lq * 4];

        __syncthreads();
        As[lq * 4 + 0][lrow] = aa.x;
        As[lq * 4 + 1][lrow] = aa.y;
        As[lq * 4 + 2][lrow] = aa.z;
        As[lq * 4 + 3][lrow] = aa.w;
        Bs[lq * 4 + 0][lrow] = wa.x;
        Bs[lq * 4 + 1][lrow] = wa.y;
        Bs[lq * 4 + 2][lrow] = wa.z;
        Bs[lq * 4 + 3][lrow] = wa.w;
        __syncthreads();

#pragma unroll
        for (int kk = 0; kk < 16; kk++) {
            const float4 a = *(const float4*)&As[kk][tr * 4];
            const float4 b = *(const float4*)&Bs[kk][tc * 4];
            acc[0][0] += a.x * b.x; acc[0][1] += a.x * b.y;
            acc[0][2] += a.x * b.z; acc[0][3] += a.x * b.w;
            acc[1][0] += a.y * b.x; acc[1][1] += a.y * b.y;
            acc[1][2] += a.y * b.z; acc[1][3] += a.y * b.w;
            acc[2][0] += a.z * b.x; acc[2][1] += a.z * b.y;
            acc[2][2] += a.z * b.z; acc[2][3] += a.z * b.w;
            acc[3][0] += a.w * b.x; acc[3][1] += a.w * b.y;
            acc[3][2] += a.w * b.z; acc[3][3] += a.w * b.w;
        }
    }

    float b4[4];
#pragma unroll
    for (int j = 0; j < 4; j++) b4[j] = bout[tc * 4 + j];

#pragma unroll
    for (int i = 0; i < 4; i++) {
        const int r = row0 + tr * 4 + i;
        if (r < N) {
            float4 ov = make_float4(acc[i][0] + b4[0], acc[i][1] + b4[1],
                                    acc[i][2] + b4[2], acc[i][3] + b4[3]);
            *(float4*)&out[r * 64 + tc * 4] = ov;
        }
    }
}

// ---------------------------------------------------------------------------
extern "C" void kernel_launch(void* const* d_in, const int* in_sizes, int n_in,
                              void* d_out, int out_size)
{
    const float* x    = (const float*)d_in[0];
    const int*   ei   = (const int*)d_in[1];
    const float* Wlin = (const float*)d_in[2];
    const float* att  = (const float*)d_in[3];
    const float* Wout = (const float*)d_in[4];
    const float* bout = (const float*)d_in[5];
    float* out = (float*)d_out;

    const int N = in_sizes[0] / 128;
    const int E = in_sizes[1] / 2;

    zero_all<<<(N * 64 + 255) / 256, 256>>>(N);
    gemm_h_kernel<<<(N + 63) / 64, 256>>>(x, Wlin, att, N);
    edge1_kernel<<<(E + 255) / 256, 256>>>(ei, E);
    edge2_kernel<<<(int)(((long long)E * 16 + 255) / 256), 256>>>(ei, E);
    gemm_out_kernel<<<(N + 63) / 64, 256>>>(Wout, bout, out, N);
}

// round 2
// speedup vs baseline: 1.1723x; 1.1723x over previous
#include <cuda_runtime.h>
#include <cuda_bf16.h>

// ---------------------------------------------------------------------------
// SimpleGAT on GB300 (sm_103a) — round 2: CSR-by-dst aggregation, no float
// atomics.
//   K1: h = x @ W_lin^T  (+ fused s_node, d_node)
//   Z : zero g_cnt
//   H : histogram  cnt[dst]++
//   S1/S2/S3: exclusive scan of cnt -> off (and cursor copy)
//   SC: scatter   srcSorted[cursor[dst]++] = src
//   AG: per-dst warp: agg[dst] = relu( (sum_e w_e h[src_e]) / (sum_e w_e + 1e-9) )
//       with w_e = exp(leaky_relu(s[src]+d[dst])) recomputed in-pass.
//       (global-max softmax stabilization skipped: cancels up to the 1e-9 eps,
//        rel effect < 1e-6)
//   K4: out = relu(agg) @ W_out^T + b_out
// ---------------------------------------------------------------------------

#define N_MAX 100000
#define E_MAX 1600000
#define CHUNK 1024
#define NPART 128

__device__ float g_h[N_MAX * 64];
__device__ float g_s[N_MAX];
__device__ float g_d[N_MAX];
__device__ float g_agg[N_MAX * 64];
__device__ int   g_cnt[N_MAX];
__device__ int   g_off[N_MAX + 1];
__device__ int   g_cur[N_MAX];
__device__ int   g_srcSorted[E_MAX];
__device__ int   g_part[NPART];

// ------------------------- K1: input GEMM + att proj -----------------------
__global__ __launch_bounds__(256) void gemm_h_kernel(
    const float* __restrict__ x, const float* __restrict__ Wlin,
    const float* __restrict__ att, int N)
{
    __shared__ float As[16][64];
    __shared__ float Bs[16][64];

    const int tid = threadIdx.x;
    const int tc  = tid & 15;
    const int tr  = tid >> 4;
    const int row0 = blockIdx.x * 64;
    const int lrow = tid >> 2;
    const int lq   = tid & 3;

    float acc[4][4];
#pragma unroll
    for (int i = 0; i < 4; i++)
#pragma unroll
        for (int j = 0; j < 4; j++) acc[i][j] = 0.f;

    for (int k0 = 0; k0 < 128; k0 += 16) {
        const int grow = row0 + lrow;
        float4 xa = make_float4(0.f, 0.f, 0.f, 0.f);
        if (grow < N)
            xa = *(const float4*)&x[grow * 128 + k0 + lq * 4];
        const float4 wa = *(const float4*)&Wlin[lrow * 128 + k0 + lq * 4];

        __syncthreads();
        As[lq * 4 + 0][lrow] = xa.x;
        As[lq * 4 + 1][lrow] = xa.y;
        As[lq * 4 + 2][lrow] = xa.z;
        As[lq * 4 + 3][lrow] = xa.w;
        Bs[lq * 4 + 0][lrow] = wa.x;
        Bs[lq * 4 + 1][lrow] = wa.y;
        Bs[lq * 4 + 2][lrow] = wa.z;
        Bs[lq * 4 + 3][lrow] = wa.w;
        __syncthreads();

#pragma unroll
        for (int kk = 0; kk < 16; kk++) {
            const float4 a = *(const float4*)&As[kk][tr * 4];
            const float4 b = *(const float4*)&Bs[kk][tc * 4];
            acc[0][0] += a.x * b.x; acc[0][1] += a.x * b.y;
            acc[0][2] += a.x * b.z; acc[0][3] += a.x * b.w;
            acc[1][0] += a.y * b.x; acc[1][1] += a.y * b.y;
            acc[1][2] += a.y * b.z; acc[1][3] += a.y * b.w;
            acc[2][0] += a.z * b.x; acc[2][1] += a.z * b.y;
            acc[2][2] += a.z * b.z; acc[2][3] += a.z * b.w;
            acc[3][0] += a.w * b.x; acc[3][1] += a.w * b.y;
            acc[3][2] += a.w * b.z; acc[3][3] += a.w * b.w;
        }
    }

    float attS[4], attD[4];
#pragma unroll
    for (int j = 0; j < 4; j++) {
        attS[j] = att[tc * 4 + j];
        attD[j] = att[64 + tc * 4 + j];
    }

#pragma unroll
    for (int i = 0; i < 4; i++) {
        const int r = row0 + tr * 4 + i;
        if (r < N) {
            float4 hv = make_float4(acc[i][0], acc[i][1], acc[i][2], acc[i][3]);
            *(float4*)&g_h[r * 64 + tc * 4] = hv;
        }
        float sp = acc[i][0] * attS[0] + acc[i][1] * attS[1] +
                   acc[i][2] * attS[2] + acc[i][3] * attS[3];
        float dp = acc[i][0] * attD[0] + acc[i][1] * attD[1] +
                   acc[i][2] * attD[2] + acc[i][3] * attD[3];
#pragma unroll
        for (int m = 8; m >= 1; m >>= 1) {
            sp += __shfl_xor_sync(0xffffffffu, sp, m);
            dp += __shfl_xor_sync(0xffffffffu, dp, m);
        }
        if (tc == 0 && r < N) {
            g_s[r] = sp;
            g_d[r] = dp;
        }
    }
}

// ------------------------- Z: zero counts ----------------------------------
__global__ void zero_cnt(int N)
{
    const int i = blockIdx.x * blockDim.x + threadIdx.x;
    if (i < N) g_cnt[i] = 0;
}

// ------------------------- H: histogram ------------------------------------
__global__ __launch_bounds__(256) void hist_kernel(const int* __restrict__ ei, int E)
{
    const int t = blockIdx.x * blockDim.x + threadIdx.x;
    if (t < E) atomicAdd(&g_cnt[ei[E + t]], 1);
}

// ------------------------- S1: per-chunk totals ----------------------------
__global__ __launch_bounds__(256) void scan_phase1(int N)
{
    const int base = blockIdx.x * CHUNK;
    const int t = threadIdx.x;
    int sum = 0;
    for (int i = t; i < CHUNK; i += 256) {
        const int idx = base + i;
        sum += (idx < N) ? g_cnt[idx] : 0;
    }
    __shared__ int warpS[8];
#pragma unroll
    for (int m = 16; m >= 1; m >>= 1) sum += __shfl_xor_sync(0xffffffffu, sum, m);
    if ((t & 31) == 0) warpS[t >> 5] = sum;
    __syncthreads();
    if (t == 0) {
        int s = 0;
#pragma unroll
        for (int i = 0; i < 8; i++) s += warpS[i];
        g_part[blockIdx.x] = s;
    }
}

// ------------------------- S2: scan chunk totals ---------------------------
__global__ void scan_phase2(int nb)
{
    if (threadIdx.x == 0) {
        int run = 0;
        for (int i = 0; i < nb; i++) {
            const int c = g_part[i];
            g_part[i] = run;
            run += c;
        }
    }
}

// ------------------------- S3: per-chunk exclusive scan --------------------
__global__ __launch_bounds__(256) void scan_phase3(int N, int E)
{
    const int base = blockIdx.x * CHUNK;
    const int t = threadIdx.x;
    const int idx0 = base + t * 4;
    int v[4];
#pragma unroll
    for (int i = 0; i < 4; i++) {
        const int idx = idx0 + i;
        v[i] = (idx < N) ? g_cnt[idx] : 0;
    }
    const int tsum = v[0] + v[1] + v[2] + v[3];

    __shared__ int sm[256];
    sm[t] = tsum;
    __syncthreads();
    for (int off = 1; off < 256; off <<= 1) {
        const int add = (t >= off) ? sm[t - off] : 0;
        __syncthreads();
        sm[t] += add;
        __syncthreads();
    }
    int run = sm[t] - tsum + g_part[blockIdx.x];
#pragma unroll
    for (int i = 0; i < 4; i++) {
        const int idx = idx0 + i;
        if (idx < N) {
            g_off[idx] = run;
            g_cur[idx] = run;
            run += v[i];
        }
    }
    if (blockIdx.x == 0 && t == 0) g_off[N] = E;
}

// ------------------------- SC: scatter src into CSR ------------------------
__global__ __launch_bounds__(256) void scatter_kernel(const int* __restrict__ ei, int E)
{
    const int t = blockIdx.x * blockDim.x + threadIdx.x;
    if (t >= E) return;
    const int src = ei[t];
    const int dst = ei[E + t];
    const int pos = atomicAdd(&g_cur[dst], 1);
    g_srcSorted[pos] = src;
}

// ------------------------- AG: register aggregation ------------------------
// One warp per dst node: 2 edges per iteration, 16 lanes per edge (float4 each).
__global__ __launch_bounds__(256) void agg_kernel(int N)
{
    const int warp = (blockIdx.x * blockDim.x + threadIdx.x) >> 5;
    if (warp >= N) return;
    const int lane = threadIdx.x & 31;
    const int part = lane & 15;
    const int sub  = lane >> 4;

    const int start = g_off[warp];
    const int end   = g_off[warp + 1];
    const float dnode = g_d[warp];

    float4 acc = make_float4(0.f, 0.f, 0.f, 0.f);
    float wsum = 0.f;

    const int cnt = end - start;
    const int iters = (cnt + 1) >> 1;
    for (int it = 0; it < iters; ++it) {
        const int e = start + it * 2 + sub;
        const bool valid = (e < end);
        const int src = g_srcSorted[valid ? e : start];
        float ev = g_s[src] + dnode;
        ev = (ev > 0.f) ? ev : 0.2f * ev;
        const float w = __expf(ev);
        if (part == 0 && valid) wsum += w;
        if (valid) {
            const float4 hv = ((const float4*)g_h)[src * 16 + part];
            acc.x += w * hv.x;
            acc.y += w * hv.y;
            acc.z += w * hv.z;
            acc.w += w * hv.w;
        }
    }

    // combine the two edge sub-groups
    acc.x += __shfl_down_sync(0xffffffffu, acc.x, 16);
    acc.y += __shfl_down_sync(0xffffffffu, acc.y, 16);
    acc.z += __shfl_down_sync(0xffffffffu, acc.z, 16);
    acc.w += __shfl_down_sync(0xffffffffu, acc.w, 16);
    wsum  += __shfl_down_sync(0xffffffffu, wsum, 16);
    const float den = __shfl_sync(0xffffffffu, wsum, 0) + 1e-9f;

    if (sub == 0) {
        const float inv = 1.f / den;
        float4 z;
        z.x = fmaxf(acc.x * inv, 0.f);
        z.y = fmaxf(acc.y * inv, 0.f);
        z.z = fmaxf(acc.z * inv, 0.f);
        z.w = fmaxf(acc.w * inv, 0.f);
        ((float4*)g_agg)[warp * 16 + part] = z;
    }
}

// ------------------------- K4: output GEMM ---------------------------------
__global__ __launch_bounds__(256) void gemm_out_kernel(
    const float* __restrict__ Wout, const float* __restrict__ bout,
    float* __restrict__ out, int N)
{
    __shared__ float As[16][64];
    __shared__ float Bs[16][64];

    const int tid = threadIdx.x;
    const int tc  = tid & 15;
    const int tr  = tid >> 4;
    const int row0 = blockIdx.x * 64;
    const int lrow = tid >> 2;
    const int lq   = tid & 3;

    float acc[4][4];
#pragma unroll
    for (int i = 0; i < 4; i++)
#pragma unroll
        for (int j = 0; j < 4; j++) acc[i][j] = 0.f;

    for (int k0 = 0; k0 < 64; k0 += 16) {
        const int grow = row0 + lrow;
        float4 aa = make_float4(0.f, 0.f, 0.f, 0.f);
        if (grow < N)
            aa = *(const float4*)&g_agg[grow * 64 + k0 + lq * 4];
        const float4 wa = *(const float4*)&Wout[lrow * 64 + k0 + lq * 4];

        __syncthreads();
        As[lq * 4 + 0][lrow] = aa.x;
        As[lq * 4 + 1][lrow] = aa.y;
        As[lq * 4 + 2][lrow] = aa.z;
        As[lq * 4 + 3][lrow] = aa.w;
        Bs[lq * 4 + 0][lrow] = wa.x;
        Bs[lq * 4 + 1][lrow] = wa.y;
        Bs[lq * 4 + 2][lrow] = wa.z;
        Bs[lq * 4 + 3][lrow] = wa.w;
        __syncthreads();

#pragma unroll
        for (int kk = 0; kk < 16; kk++) {
            const float4 a = *(const float4*)&As[kk][tr * 4];
            const float4 b = *(const float4*)&Bs[kk][tc * 4];
            acc[0][0] += a.x * b.x; acc[0][1] += a.x * b.y;
            acc[0][2] += a.x * b.z; acc[0][3] += a.x * b.w;
            acc[1][0] += a.y * b.x; acc[1][1] += a.y * b.y;
            acc[1][2] += a.y * b.z; acc[1][3] += a.y * b.w;
            acc[2][0] += a.z * b.x; acc[2][1] += a.z * b.y;
            acc[2][2] += a.z * b.z; acc[2][3] += a.z * b.w;
            acc[3][0] += a.w * b.x; acc[3][1] += a.w * b.y;
            acc[3][2] += a.w * b.z; acc[3][3] += a.w * b.w;
        }
    }

    float b4[4];
#pragma unroll
    for (int j = 0; j < 4; j++) b4[j] = bout[tc * 4 + j];

#pragma unroll
    for (int i = 0; i < 4; i++) {
        const int r = row0 + tr * 4 + i;
        if (r < N) {
            float4 ov = make_float4(acc[i][0] + b4[0], acc[i][1] + b4[1],
                                    acc[i][2] + b4[2], acc[i][3] + b4[3]);
            *(float4*)&out[r * 64 + tc * 4] = ov;
        }
    }
}

// ---------------------------------------------------------------------------
extern "C" void kernel_launch(void* const* d_in, const int* in_sizes, int n_in,
                              void* d_out, int out_size)
{
    const float* x    = (const float*)d_in[0];
    const int*   ei   = (const int*)d_in[1];
    const float* Wlin = (const float*)d_in[2];
    const float* att  = (const float*)d_in[3];
    const float* Wout = (const float*)d_in[4];
    const float* bout = (const float*)d_in[5];
    float* out = (float*)d_out;

    const int N = in_sizes[0] / 128;
    const int E = in_sizes[1] / 2;
    const int nb = (N + CHUNK - 1) / CHUNK;

    zero_cnt<<<(N + 255) / 256, 256>>>(N);
    gemm_h_kernel<<<(N + 63) / 64, 256>>>(x, Wlin, att, N);
    hist_kernel<<<(E + 255) / 256, 256>>>(ei, E);
    scan_phase1<<<nb, 256>>>(N);
    scan_phase2<<<1, 32>>>(nb);
    scan_phase3<<<nb, 256>>>(N, E);
    scatter_kernel<<<(E + 255) / 256, 256>>>(ei, E);
    agg_kernel<<<(N * 32 + 255) / 256, 256>>>(N);
    gemm_out_kernel<<<(N + 63) / 64, 256>>>(Wout, bout, out, N);
}

// round 4
// speedup vs baseline: 1.3181x; 1.1244x over previous
#include <cuda_runtime.h>
#include <cuda_fp16.h>
#include <cuda_bf16.h>

// ---------------------------------------------------------------------------
// SimpleGAT on GB300 (sm_103a) — round 4: round-3 pipeline with the g_hh
// store-width bug fixed (uint2 -> uint4: all 8 columns per thread now stored).
//  * GEMMs use packed fma.rn.f32x2 (FFMA2): 2x fp32 FMA throughput.
//  * h stored as fp16 (half2) — only the edge gather reads it; s/d projections
//    come from the fp32 accumulators. Halves agg's L2 traffic.
//  * CSR-by-dst aggregation (no float atomics), denominator folded into the
//    same register pass. Global-max softmax stabilization skipped (cancels
//    up to the 1e-9 eps; rel effect < 1e-6).
// ---------------------------------------------------------------------------

#define N_MAX 100000
#define E_MAX 1600000
#define CHUNK 1024
#define NPART 128

__device__ __half2 g_hh[N_MAX * 32];   // h as half2, row = 32 half2 = 128B
__device__ float g_s[N_MAX];
__device__ float g_d[N_MAX];
__device__ float g_agg[N_MAX * 64];
__device__ int   g_cnt[N_MAX];
__device__ int   g_off[N_MAX + 1];
__device__ int   g_cur[N_MAX];
__device__ int   g_srcSorted[E_MAX];
__device__ int   g_part[NPART];

#define FMA2(d, a, b) \
    asm("fma.rn.f32x2 %0, %1, %2, %3;" : "=l"(d) : "l"(a), "l"(b), "l"(d))

__device__ __forceinline__ unsigned long long dup_f32x2(float v)
{
    unsigned long long r;
    asm("mov.b64 %0, {%1, %1};" : "=l"(r) : "r"(__float_as_uint(v)));
    return r;
}

union F2U64 {
    unsigned long long u;
    float2 f;
};

// ------------------------- K1: input GEMM + att proj -----------------------
// Tile 128 rows x 64 cols, 128 threads, 8x8 microtile, rows paired in f32x2.
__global__ __launch_bounds__(128) void gemm_h_kernel(
    const float* __restrict__ x, const float* __restrict__ Wlin,
    const float* __restrict__ att, int N)
{
    __shared__ float As[16][128];   // As[k][row]
    __shared__ float Bs[16][64];    // Bs[k][col] = Wlin[col][k]

    const int tid = threadIdx.x;
    const int tc  = tid & 7;        // col group: cols tc*8 .. tc*8+7
    const int tr  = tid >> 3;       // row group: rows tr*8 .. tr*8+7
    const int row0 = blockIdx.x * 128;

    // fused: zero g_cnt for the histogram
    for (int i = blockIdx.x * 128 + tid; i < N; i += gridDim.x * 128)
        g_cnt[i] = 0;

    unsigned long long acc[4][8];
#pragma unroll
    for (int rp = 0; rp < 4; rp++)
#pragma unroll
        for (int c = 0; c < 8; c++) acc[rp][c] = 0ull;

    const int xrow = row0 + tid;
    const int wrow = tid >> 1;
    const int wq0  = (tid & 1) * 2;

    for (int k0 = 0; k0 < 128; k0 += 16) {
        __syncthreads();
        // load x rows (one row per thread, 4 float4)
#pragma unroll
        for (int q = 0; q < 4; q++) {
            float4 v = make_float4(0.f, 0.f, 0.f, 0.f);
            if (xrow < N) v = *(const float4*)&x[xrow * 128 + k0 + q * 4];
            As[q * 4 + 0][tid] = v.x;
            As[q * 4 + 1][tid] = v.y;
            As[q * 4 + 2][tid] = v.z;
            As[q * 4 + 3][tid] = v.w;
        }
        // load W (2 float4 per thread)
#pragma unroll
        for (int qi = 0; qi < 2; qi++) {
            const int q = wq0 + qi;
            const float4 w = *(const float4*)&Wlin[wrow * 128 + k0 + q * 4];
            Bs[q * 4 + 0][wrow] = w.x;
            Bs[q * 4 + 1][wrow] = w.y;
            Bs[q * 4 + 2][wrow] = w.z;
            Bs[q * 4 + 3][wrow] = w.w;
        }
        __syncthreads();

#pragma unroll
        for (int kk = 0; kk < 16; kk++) {
            const ulonglong2 aA = *(const ulonglong2*)&As[kk][tr * 8];
            const ulonglong2 aB = *(const ulonglong2*)&As[kk][tr * 8 + 4];
            unsigned long long a2[4] = { aA.x, aA.y, aB.x, aB.y };
            const float4 b0 = *(const float4*)&Bs[kk][tc * 8];
            const float4 b1 = *(const float4*)&Bs[kk][tc * 8 + 4];
            unsigned long long bb[8];
            bb[0] = dup_f32x2(b0.x); bb[1] = dup_f32x2(b0.y);
            bb[2] = dup_f32x2(b0.z); bb[3] = dup_f32x2(b0.w);
            bb[4] = dup_f32x2(b1.x); bb[5] = dup_f32x2(b1.y);
            bb[6] = dup_f32x2(b1.z); bb[7] = dup_f32x2(b1.w);
#pragma unroll
            for (int rp = 0; rp < 4; rp++)
#pragma unroll
                for (int c = 0; c < 8; c++)
                    FMA2(acc[rp][c], a2[rp], bb[c]);
        }
    }

    float attS[8], attD[8];
#pragma unroll
    for (int c = 0; c < 8; c++) {
        attS[c] = att[tc * 8 + c];
        attD[c] = att[64 + tc * 8 + c];
    }

#pragma unroll
    for (int r = 0; r < 8; r++) {
        const int rp = r >> 1;
        const int hi = r & 1;
        float hv[8];
#pragma unroll
        for (int c = 0; c < 8; c++) {
            F2U64 u; u.u = acc[rp][c];
            hv[c] = hi ? u.f.y : u.f.x;
        }
        const int row = row0 + tr * 8 + r;
        if (row < N) {
            __half2 p[4];
#pragma unroll
            for (int j = 0; j < 4; j++)
                p[j] = __floats2half2_rn(hv[2 * j], hv[2 * j + 1]);
            *(uint4*)&g_hh[row * 32 + tc * 4] = *(uint4*)p;   // FIXED: 16B store
        }
        float sp = 0.f, dp = 0.f;
#pragma unroll
        for (int c = 0; c < 8; c++) {
            sp += hv[c] * attS[c];
            dp += hv[c] * attD[c];
        }
#pragma unroll
        for (int m = 4; m >= 1; m >>= 1) {
            sp += __shfl_xor_sync(0xffffffffu, sp, m);
            dp += __shfl_xor_sync(0xffffffffu, dp, m);
        }
        if (tc == 0 && row < N) {
            g_s[row] = sp;
            g_d[row] = dp;
        }
    }
}

// ------------------------- H: histogram ------------------------------------
__global__ __launch_bounds__(256) void hist_kernel(const int* __restrict__ ei, int E)
{
    const int t = blockIdx.x * blockDim.x + threadIdx.x;
    if (t < E) atomicAdd(&g_cnt[ei[E + t]], 1);
}

// ------------------------- S1: per-chunk totals (vectorized) ---------------
__global__ __launch_bounds__(256) void scan_phase1(int N)
{
    const int base = blockIdx.x * CHUNK;
    const int t = threadIdx.x;
    const int idx = base + t * 4;
    int sum = 0;
    if (idx + 3 < N) {
        const int4 v = *(const int4*)&g_cnt[idx];
        sum = v.x + v.y + v.z + v.w;
    } else {
#pragma unroll
        for (int i = 0; i < 4; i++)
            if (idx + i < N) sum += g_cnt[idx + i];
    }
    __shared__ int warpS[8];
#pragma unroll
    for (int m = 16; m >= 1; m >>= 1) sum += __shfl_xor_sync(0xffffffffu, sum, m);
    if ((t & 31) == 0) warpS[t >> 5] = sum;
    __syncthreads();
    if (t == 0) {
        int s = 0;
#pragma unroll
        for (int i = 0; i < 8; i++) s += warpS[i];
        g_part[blockIdx.x] = s;
    }
}

// ------------------------- S2: scan chunk totals ---------------------------
__global__ void scan_phase2(int nb)
{
    const int t = threadIdx.x;
    __shared__ int sm[NPART];
    sm[t] = (t < nb) ? g_part[t] : 0;
    __syncthreads();
    for (int off = 1; off < NPART; off <<= 1) {
        const int add = (t >= off) ? sm[t - off] : 0;
        __syncthreads();
        sm[t] += add;
        __syncthreads();
    }
    if (t < nb) {
        const int excl = (t == 0) ? 0 : sm[t - 1];
        g_part[t] = excl;
    }
}

// ------------------------- S3: per-chunk exclusive scan --------------------
__global__ __launch_bounds__(256) void scan_phase3(int N, int E)
{
    const int base = blockIdx.x * CHUNK;
    const int t = threadIdx.x;
    const int idx0 = base + t * 4;
    int v[4];
#pragma unroll
    for (int i = 0; i < 4; i++) {
        const int idx = idx0 + i;
        v[i] = (idx < N) ? g_cnt[idx] : 0;
    }
    const int tsum = v[0] + v[1] + v[2] + v[3];

    __shared__ int sm[256];
    sm[t] = tsum;
    __syncthreads();
    for (int off = 1; off < 256; off <<= 1) {
        const int add = (t >= off) ? sm[t - off] : 0;
        __syncthreads();
        sm[t] += add;
        __syncthreads();
    }
    int run = sm[t] - tsum + g_part[blockIdx.x];
#pragma unroll
    for (int i = 0; i < 4; i++) {
        const int idx = idx0 + i;
        if (idx < N) {
            g_off[idx] = run;
            g_cur[idx] = run;
            run += v[i];
        }
    }
    if (blockIdx.x == 0 && t == 0) g_off[N] = E;
}

// ------------------------- SC: scatter src into CSR ------------------------
__global__ __launch_bounds__(256) void scatter_kernel(const int* __restrict__ ei, int E)
{
    const int t = blockIdx.x * blockDim.x + threadIdx.x;
    if (t >= E) return;
    const int src = ei[t];
    const int dst = ei[E + t];
    const int pos = atomicAdd(&g_cur[dst], 1);
    g_srcSorted[pos] = src;
}

// ------------------------- AG: register aggregation ------------------------
// One warp per dst node: 4 edges per iteration, 8 lanes per edge (16B each).
__global__ __launch_bounds__(256) void agg_kernel(int N)
{
    const int warp = (blockIdx.x * blockDim.x + threadIdx.x) >> 5;
    if (warp >= N) return;
    const int lane = threadIdx.x & 31;
    const int part = lane & 7;     // 16B chunk of the 128B fp16 row
    const int sub  = lane >> 3;    // which of the 4 edges this iter

    const int start = g_off[warp];
    const int end   = g_off[warp + 1];
    const float dnode = g_d[warp];

    unsigned long long acc2[4] = {0ull, 0ull, 0ull, 0ull};
    float wsum = 0.f;

    const int cnt = end - start;
    const int iters = (cnt + 3) >> 2;
    for (int it = 0; it < iters; ++it) {
        const int e = start + it * 4 + sub;
        const bool valid = (e < end);
        const int src = g_srcSorted[valid ? e : 0];   // FIXED: in-bounds dummy
        float ev = g_s[src] + dnode;
        ev = (ev > 0.f) ? ev : 0.2f * ev;
        const float w = valid ? __expf(ev) : 0.f;
        if (part == 0) wsum += w;
        const unsigned long long w2 = dup_f32x2(w);
        const uint4 hvu = *(const uint4*)(((const char*)g_hh) + ((size_t)src * 128 + part * 16));
        const __half2* hp = (const __half2*)&hvu;
#pragma unroll
        for (int j = 0; j < 4; j++) {
            F2U64 hf; hf.f = __half22float2(hp[j]);
            FMA2(acc2[j], hf.u, w2);
        }
    }

    // sum over the 4 edge sub-groups (lanes with same part)
#pragma unroll
    for (int j = 0; j < 4; j++) {
        F2U64 a; a.u = acc2[j];
        a.f.x += __shfl_xor_sync(0xffffffffu, a.f.x, 8);
        a.f.y += __shfl_xor_sync(0xffffffffu, a.f.y, 8);
        a.f.x += __shfl_xor_sync(0xffffffffu, a.f.x, 16);
        a.f.y += __shfl_xor_sync(0xffffffffu, a.f.y, 16);
        acc2[j] = a.u;
    }
    wsum += __shfl_xor_sync(0xffffffffu, wsum, 8);
    wsum += __shfl_xor_sync(0xffffffffu, wsum, 16);
    const float den = __shfl_sync(0xffffffffu, wsum, 0) + 1e-9f;

    if (sub == 0) {
        const float inv = 1.f / den;
        float o[8];
#pragma unroll
        for (int j = 0; j < 4; j++) {
            F2U64 a; a.u = acc2[j];
            o[2 * j]     = fmaxf(a.f.x * inv, 0.f);
            o[2 * j + 1] = fmaxf(a.f.y * inv, 0.f);
        }
        float4* dst4 = (float4*)&g_agg[warp * 64 + part * 8];
        dst4[0] = make_float4(o[0], o[1], o[2], o[3]);
        dst4[1] = make_float4(o[4], o[5], o[6], o[7]);
    }
}

// ------------------------- K4: output GEMM ---------------------------------
// out = agg @ W_out^T + b_out (relu already applied in agg). Same microkernel.
__global__ __launch_bounds__(128) void gemm_out_kernel(
    const float* __restrict__ Wout, const float* __restrict__ bout,
    float* __restrict__ out, int N)
{
    __shared__ float As[16][128];
    __shared__ float Bs[16][64];

    const int tid = threadIdx.x;
    const int tc  = tid & 7;
    const int tr  = tid >> 3;
    const int row0 = blockIdx.x * 128;

    unsigned long long acc[4][8];
#pragma unroll
    for (int rp = 0; rp < 4; rp++)
#pragma unroll
        for (int c = 0; c < 8; c++) acc[rp][c] = 0ull;

    const int arow = row0 + tid;
    const int wrow = tid >> 1;
    const int wq0  = (tid & 1) * 2;

    for (int k0 = 0; k0 < 64; k0 += 16) {
        __syncthreads();
#pragma unroll
        for (int q = 0; q < 4; q++) {
            float4 v = make_float4(0.f, 0.f, 0.f, 0.f);
            if (arow < N) v = *(const float4*)&g_agg[arow * 64 + k0 + q * 4];
            As[q * 4 + 0][tid] = v.x;
            As[q * 4 + 1][tid] = v.y;
            As[q * 4 + 2][tid] = v.z;
            As[q * 4 + 3][tid] = v.w;
        }
#pragma unroll
        for (int qi = 0; qi < 2; qi++) {
            const int q = wq0 + qi;
            const float4 w = *(const float4*)&Wout[wrow * 64 + k0 + q * 4];
            Bs[q * 4 + 0][wrow] = w.x;
            Bs[q * 4 + 1][wrow] = w.y;
            Bs[q * 4 + 2][wrow] = w.z;
            Bs[q * 4 + 3][wrow] = w.w;
        }
        __syncthreads();

#pragma unroll
        for (int kk = 0; kk < 16; kk++) {
            const ulonglong2 aA = *(const ulonglong2*)&As[kk][tr * 8];
            const ulonglong2 aB = *(const ulonglong2*)&As[kk][tr * 8 + 4];
            unsigned long long a2[4] = { aA.x, aA.y, aB.x, aB.y };
            const float4 b0 = *(const float4*)&Bs[kk][tc * 8];
            const float4 b1 = *(const float4*)&Bs[kk][tc * 8 + 4];
            unsigned long long bb[8];
            bb[0] = dup_f32x2(b0.x); bb[1] = dup_f32x2(b0.y);
            bb[2] = dup_f32x2(b0.z); bb[3] = dup_f32x2(b0.w);
            bb[4] = dup_f32x2(b1.x); bb[5] = dup_f32x2(b1.y);
            bb[6] = dup_f32x2(b1.z); bb[7] = dup_f32x2(b1.w);
#pragma unroll
            for (int rp = 0; rp < 4; rp++)
#pragma unroll
                for (int c = 0; c < 8; c++)
                    FMA2(acc[rp][c], a2[rp], bb[c]);
        }
    }

    float b8[8];
#pragma unroll
    for (int c = 0; c < 8; c++) b8[c] = bout[tc * 8 + c];

#pragma unroll
    for (int r = 0; r < 8; r++) {
        const int rp = r >> 1;
        const int hi = r & 1;
        const int row = row0 + tr * 8 + r;
        if (row >= N) continue;
        float o[8];
#pragma unroll
        for (int c = 0; c < 8; c++) {
            F2U64 u; u.u = acc[rp][c];
            o[c] = (hi ? u.f.y : u.f.x) + b8[c];
        }
        float4* dst4 = (float4*)&out[row * 64 + tc * 8];
        dst4[0] = make_float4(o[0], o[1], o[2], o[3]);
        dst4[1] = make_float4(o[4], o[5], o[6], o[7]);
    }
}

// ---------------------------------------------------------------------------
extern "C" void kernel_launch(void* const* d_in, const int* in_sizes, int n_in,
                              void* d_out, int out_size)
{
    const float* x    = (const float*)d_in[0];
    const int*   ei   = (const int*)d_in[1];
    const float* Wlin = (const float*)d_in[2];
    const float* att  = (const float*)d_in[3];
    const float* Wout = (const float*)d_in[4];
    const float* bout = (const float*)d_in[5];
    float* out = (float*)d_out;

    const int N = in_sizes[0] / 128;
    const int E = in_sizes[1] / 2;
    const int nb = (N + CHUNK - 1) / CHUNK;

    gemm_h_kernel<<<(N + 127) / 128, 128>>>(x, Wlin, att, N);
    hist_kernel<<<(E + 255) / 256, 256>>>(ei, E);
    scan_phase1<<<nb, 256>>>(N);
    scan_phase2<<<1, NPART>>>(nb);
    scan_phase3<<<nb, 256>>>(N, E);
    scatter_kernel<<<(E + 255) / 256, 256>>>(ei, E);
    agg_kernel<<<(N * 32 + 255) / 256, 256>>>(N);
    gemm_out_kernel<<<(N + 127) / 128, 128>>>(Wout, bout, out, N);
}

// round 5
// speedup vs baseline: 1.4160x; 1.0743x over previous
#include <cuda_runtime.h>
#include <cuda_fp16.h>
#include <cuda_bf16.h>

// ---------------------------------------------------------------------------
// SimpleGAT on GB300 (sm_103a) — round 5: graph restructure.
//  * CSR build (zero/hist/scan/scatter) forked onto a second stream,
//    overlapped with the input GEMM (they share no data). Event join before
//    the aggregation kernel. One scan launch removed (partials scanned
//    in-block in phase3).
//  * GEMMs: packed fma.rn.f32x2 (2x fp32 throughput), rows paired in lanes.
//  * h stored fp16 for the edge gather; s/d from fp32 accumulators.
//  * CSR-by-dst aggregation, denominator fused; global-max softmax
//    stabilization skipped (cancels up to the 1e-9 eps; rel effect < 1e-6).
// ---------------------------------------------------------------------------

#define N_MAX 100000
#define E_MAX 1600000
#define CHUNK 1024
#define NPART 128

__device__ __half2 g_hh[N_MAX * 32];   // h as half2, row = 32 half2 = 128B
__device__ float g_s[N_MAX];
__device__ float g_d[N_MAX];
__device__ float g_agg[N_MAX * 64];
__device__ int   g_cnt[N_MAX];
__device__ int   g_off[N_MAX + 1];
__device__ int   g_cur[N_MAX];
__device__ int   g_srcSorted[E_MAX];
__device__ int   g_part[NPART];

#define FMA2(d, a, b) \
    asm("fma.rn.f32x2 %0, %1, %2, %3;" : "=l"(d) : "l"(a), "l"(b), "l"(d))

__device__ __forceinline__ unsigned long long dup_f32x2(float v)
{
    unsigned long long r;
    asm("mov.b64 %0, {%1, %1};" : "=l"(r) : "r"(__float_as_uint(v)));
    return r;
}

union F2U64 {
    unsigned long long u;
    float2 f;
};

// ------------------------- K1: input GEMM + att proj -----------------------
// Tile 128 rows x 64 cols, 128 threads, 8x8 microtile, rows paired in f32x2.
__global__ __launch_bounds__(128) void gemm_h_kernel(
    const float* __restrict__ x, const float* __restrict__ Wlin,
    const float* __restrict__ att, int N)
{
    __shared__ float As[16][128];   // As[k][row]
    __shared__ float Bs[16][64];    // Bs[k][col] = Wlin[col][k]

    const int tid = threadIdx.x;
    const int tc  = tid & 7;        // col group: cols tc*8 .. tc*8+7
    const int tr  = tid >> 3;       // row group: rows tr*8 .. tr*8+7
    const int row0 = blockIdx.x * 128;

    unsigned long long acc[4][8];
#pragma unroll
    for (int rp = 0; rp < 4; rp++)
#pragma unroll
        for (int c = 0; c < 8; c++) acc[rp][c] = 0ull;

    const int xrow = row0 + tid;
    const int wrow = tid >> 1;
    const int wq0  = (tid & 1) * 2;

    for (int k0 = 0; k0 < 128; k0 += 16) {
        __syncthreads();
#pragma unroll
        for (int q = 0; q < 4; q++) {
            float4 v = make_float4(0.f, 0.f, 0.f, 0.f);
            if (xrow < N) v = *(const float4*)&x[xrow * 128 + k0 + q * 4];
            As[q * 4 + 0][tid] = v.x;
            As[q * 4 + 1][tid] = v.y;
            As[q * 4 + 2][tid] = v.z;
            As[q * 4 + 3][tid] = v.w;
        }
#pragma unroll
        for (int qi = 0; qi < 2; qi++) {
            const int q = wq0 + qi;
            const float4 w = *(const float4*)&Wlin[wrow * 128 + k0 + q * 4];
            Bs[q * 4 + 0][wrow] = w.x;
            Bs[q * 4 + 1][wrow] = w.y;
            Bs[q * 4 + 2][wrow] = w.z;
            Bs[q * 4 + 3][wrow] = w.w;
        }
        __syncthreads();

#pragma unroll
        for (int kk = 0; kk < 16; kk++) {
            const ulonglong2 aA = *(const ulonglong2*)&As[kk][tr * 8];
            const ulonglong2 aB = *(const ulonglong2*)&As[kk][tr * 8 + 4];
            unsigned long long a2[4] = { aA.x, aA.y, aB.x, aB.y };
            const float4 b0 = *(const float4*)&Bs[kk][tc * 8];
            const float4 b1 = *(const float4*)&Bs[kk][tc * 8 + 4];
            unsigned long long bb[8];
            bb[0] = dup_f32x2(b0.x); bb[1] = dup_f32x2(b0.y);
            bb[2] = dup_f32x2(b0.z); bb[3] = dup_f32x2(b0.w);
            bb[4] = dup_f32x2(b1.x); bb[5] = dup_f32x2(b1.y);
            bb[6] = dup_f32x2(b1.z); bb[7] = dup_f32x2(b1.w);
#pragma unroll
            for (int rp = 0; rp < 4; rp++)
#pragma unroll
                for (int c = 0; c < 8; c++)
                    FMA2(acc[rp][c], a2[rp], bb[c]);
        }
    }

    float attS[8], attD[8];
#pragma unroll
    for (int c = 0; c < 8; c++) {
        attS[c] = att[tc * 8 + c];
        attD[c] = att[64 + tc * 8 + c];
    }

#pragma unroll
    for (int r = 0; r < 8; r++) {
        const int rp = r >> 1;
        const int hi = r & 1;
        float hv[8];
#pragma unroll
        for (int c = 0; c < 8; c++) {
            F2U64 u; u.u = acc[rp][c];
            hv[c] = hi ? u.f.y : u.f.x;
        }
        const int row = row0 + tr * 8 + r;
        if (row < N) {
            __half2 p[4];
#pragma unroll
            for (int j = 0; j < 4; j++)
                p[j] = __floats2half2_rn(hv[2 * j], hv[2 * j + 1]);
            *(uint4*)&g_hh[row * 32 + tc * 4] = *(uint4*)p;
        }
        float sp = 0.f, dp = 0.f;
#pragma unroll
        for (int c = 0; c < 8; c++) {
            sp += hv[c] * attS[c];
            dp += hv[c] * attD[c];
        }
#pragma unroll
        for (int m = 4; m >= 1; m >>= 1) {
            sp += __shfl_xor_sync(0xffffffffu, sp, m);
            dp += __shfl_xor_sync(0xffffffffu, dp, m);
        }
        if (tc == 0 && row < N) {
            g_s[row] = sp;
            g_d[row] = dp;
        }
    }
}

// ------------------------- Z: zero counts (stream B head) ------------------
__global__ __launch_bounds__(256) void zero_cnt(int N)
{
    const int i = blockIdx.x * blockDim.x + threadIdx.x;
    const int i4 = i * 4;
    if (i4 + 3 < N) {
        *(int4*)&g_cnt[i4] = make_int4(0, 0, 0, 0);
    } else {
        for (int j = 0; j < 4; j++)
            if (i4 + j < N) g_cnt[i4 + j] = 0;
    }
}

// ------------------------- H: histogram (4 edges/thread) -------------------
__global__ __launch_bounds__(256) void hist_kernel(const int* __restrict__ ei, int E)
{
    const int t = blockIdx.x * blockDim.x + threadIdx.x;
    const int e4 = t * 4;
    if (e4 + 3 < E) {
        const int4 d = *(const int4*)&ei[E + e4];
        atomicAdd(&g_cnt[d.x], 1);
        atomicAdd(&g_cnt[d.y], 1);
        atomicAdd(&g_cnt[d.z], 1);
        atomicAdd(&g_cnt[d.w], 1);
    } else {
        for (int j = 0; j < 4; j++)
            if (e4 + j < E) atomicAdd(&g_cnt[ei[E + e4 + j]], 1);
    }
}

// ------------------------- S1: per-chunk totals (vectorized) ---------------
__global__ __launch_bounds__(256) void scan_phase1(int N)
{
    const int base = blockIdx.x * CHUNK;
    const int t = threadIdx.x;
    const int idx = base + t * 4;
    int sum = 0;
    if (idx + 3 < N) {
        const int4 v = *(const int4*)&g_cnt[idx];
        sum = v.x + v.y + v.z + v.w;
    } else {
#pragma unroll
        for (int i = 0; i < 4; i++)
            if (idx + i < N) sum += g_cnt[idx + i];
    }
    __shared__ int warpS[8];
#pragma unroll
    for (int m = 16; m >= 1; m >>= 1) sum += __shfl_xor_sync(0xffffffffu, sum, m);
    if ((t & 31) == 0) warpS[t >> 5] = sum;
    __syncthreads();
    if (t == 0) {
        int s = 0;
#pragma unroll
        for (int i = 0; i < 8; i++) s += warpS[i];
        g_part[blockIdx.x] = s;
    }
}

// ------------------------- S3: exclusive scan (partials scanned in-block) --
__global__ __launch_bounds__(256) void scan_phase3(int N, int E, int nb)
{
    const int t = threadIdx.x;

    // scan the chunk totals locally (<= NPART ints; Hillis-Steele)
    __shared__ int psm[NPART];
    if (t < NPART) psm[t] = (t < nb) ? g_part[t] : 0;
    __syncthreads();
    for (int off = 1; off < NPART; off <<= 1) {
        int add = 0;
        if (t < NPART && t >= off) add = psm[t - off];
        __syncthreads();
        if (t < NPART) psm[t] += add;
        __syncthreads();
    }
    const int chunkBase = (blockIdx.x == 0) ? 0 : psm[blockIdx.x - 1];

    const int base = blockIdx.x * CHUNK;
    const int idx0 = base + t * 4;
    int v[4];
#pragma unroll
    for (int i = 0; i < 4; i++) {
        const int idx = idx0 + i;
        v[i] = (idx < N) ? g_cnt[idx] : 0;
    }
    const int tsum = v[0] + v[1] + v[2] + v[3];

    __shared__ int sm[256];
    sm[t] = tsum;
    __syncthreads();
    for (int off = 1; off < 256; off <<= 1) {
        const int add = (t >= off) ? sm[t - off] : 0;
        __syncthreads();
        sm[t] += add;
        __syncthreads();
    }
    int run = sm[t] - tsum + chunkBase;
#pragma unroll
    for (int i = 0; i < 4; i++) {
        const int idx = idx0 + i;
        if (idx < N) {
            g_off[idx] = run;
            g_cur[idx] = run;
            run += v[i];
        }
    }
    if (blockIdx.x == 0 && t == 0) g_off[N] = E;
}

// ------------------------- SC: scatter src into CSR ------------------------
__global__ __launch_bounds__(256) void scatter_kernel(const int* __restrict__ ei, int E)
{
    const int t = blockIdx.x * blockDim.x + threadIdx.x;
    const int e4 = t * 4;
    if (e4 + 3 < E) {
        const int4 s = *(const int4*)&ei[e4];
        const int4 d = *(const int4*)&ei[E + e4];
        g_srcSorted[atomicAdd(&g_cur[d.x], 1)] = s.x;
        g_srcSorted[atomicAdd(&g_cur[d.y], 1)] = s.y;
        g_srcSorted[atomicAdd(&g_cur[d.z], 1)] = s.z;
        g_srcSorted[atomicAdd(&g_cur[d.w], 1)] = s.w;
    } else {
        for (int j = 0; j < 4; j++) {
            const int e = e4 + j;
            if (e < E)
                g_srcSorted[atomicAdd(&g_cur[ei[E + e]], 1)] = ei[e];
        }
    }
}

// ------------------------- AG: register aggregation ------------------------
// One warp per dst node: 4 edges per iteration, 8 lanes per edge (16B each).
__global__ __launch_bounds__(256) void agg_kernel(int N)
{
    const int warp = (blockIdx.x * blockDim.x + threadIdx.x) >> 5;
    if (warp >= N) return;
    const int lane = threadIdx.x & 31;
    const int part = lane & 7;     // 16B chunk of the 128B fp16 row
    const int sub  = lane >> 3;    // which of the 4 edges this iter

    const int start = g_off[warp];
    const int end   = g_off[warp + 1];
    const float dnode = g_d[warp];

    unsigned long long acc2[4] = {0ull, 0ull, 0ull, 0ull};
    float wsum = 0.f;

    const int cnt = end - start;
    const int iters = (cnt + 3) >> 2;
    for (int it = 0; it < iters; ++it) {
        const int e = start + it * 4 + sub;
        const bool valid = (e < end);
        const int src = g_srcSorted[valid ? e : 0];
        float ev = g_s[src] + dnode;
        ev = (ev > 0.f) ? ev : 0.2f * ev;
        const float w = valid ? __expf(ev) : 0.f;
        if (part == 0) wsum += w;
        const unsigned long long w2 = dup_f32x2(w);
        const uint4 hvu = *(const uint4*)(((const char*)g_hh) + ((size_t)src * 128 + part * 16));
        const __half2* hp = (const __half2*)&hvu;
#pragma unroll
        for (int j = 0; j < 4; j++) {
            F2U64 hf; hf.f = __half22float2(hp[j]);
            FMA2(acc2[j], hf.u, w2);
        }
    }

#pragma unroll
    for (int j = 0; j < 4; j++) {
        F2U64 a; a.u = acc2[j];
        a.f.x += __shfl_xor_sync(0xffffffffu, a.f.x, 8);
        a.f.y += __shfl_xor_sync(0xffffffffu, a.f.y, 8);
        a.f.x += __shfl_xor_sync(0xffffffffu, a.f.x, 16);
        a.f.y += __shfl_xor_sync(0xffffffffu, a.f.y, 16);
        acc2[j] = a.u;
    }
    wsum += __shfl_xor_sync(0xffffffffu, wsum, 8);
    wsum += __shfl_xor_sync(0xffffffffu, wsum, 16);
    const float den = __shfl_sync(0xffffffffu, wsum, 0) + 1e-9f;

    if (sub == 0) {
        const float inv = 1.f / den;
        float o[8];
#pragma unroll
        for (int j = 0; j < 4; j++) {
            F2U64 a; a.u = acc2[j];
            o[2 * j]     = fmaxf(a.f.x * inv, 0.f);
            o[2 * j + 1] = fmaxf(a.f.y * inv, 0.f);
        }
        float4* dst4 = (float4*)&g_agg[warp * 64 + part * 8];
        dst4[0] = make_float4(o[0], o[1], o[2], o[3]);
        dst4[1] = make_float4(o[4], o[5], o[6], o[7]);
    }
}

// ------------------------- K4: output GEMM ---------------------------------
__global__ __launch_bounds__(128) void gemm_out_kernel(
    const float* __restrict__ Wout, const float* __restrict__ bout,
    float* __restrict__ out, int N)
{
    __shared__ float As[16][128];
    __shared__ float Bs[16][64];

    const int tid = threadIdx.x;
    const int tc  = tid & 7;
    const int tr  = tid >> 3;
    const int row0 = blockIdx.x * 128;

    unsigned long long acc[4][8];
#pragma unroll
    for (int rp = 0; rp < 4; rp++)
#pragma unroll
        for (int c = 0; c < 8; c++) acc[rp][c] = 0ull;

    const int arow = row0 + tid;
    const int wrow = tid >> 1;
    const int wq0  = (tid & 1) * 2;

    for (int k0 = 0; k0 < 64; k0 += 16) {
        __syncthreads();
#pragma unroll
        for (int q = 0; q < 4; q++) {
            float4 v = make_float4(0.f, 0.f, 0.f, 0.f);
            if (arow < N) v = *(const float4*)&g_agg[arow * 64 + k0 + q * 4];
            As[q * 4 + 0][tid] = v.x;
            As[q * 4 + 1][tid] = v.y;
            As[q * 4 + 2][tid] = v.z;
            As[q * 4 + 3][tid] = v.w;
        }
#pragma unroll
        for (int qi = 0; qi < 2; qi++) {
            const int q = wq0 + qi;
            const float4 w = *(const float4*)&Wout[wrow * 64 + k0 + q * 4];
            Bs[q * 4 + 0][wrow] = w.x;
            Bs[q * 4 + 1][wrow] = w.y;
            Bs[q * 4 + 2][wrow] = w.z;
            Bs[q * 4 + 3][wrow] = w.w;
        }
        __syncthreads();

#pragma unroll
        for (int kk = 0; kk < 16; kk++) {
            const ulonglong2 aA = *(const ulonglong2*)&As[kk][tr * 8];
            const ulonglong2 aB = *(const ulonglong2*)&As[kk][tr * 8 + 4];
            unsigned long long a2[4] = { aA.x, aA.y, aB.x, aB.y };
            const float4 b0 = *(const float4*)&Bs[kk][tc * 8];
            const float4 b1 = *(const float4*)&Bs[kk][tc * 8 + 4];
            unsigned long long bb[8];
            bb[0] = dup_f32x2(b0.x); bb[1] = dup_f32x2(b0.y);
            bb[2] = dup_f32x2(b0.z); bb[3] = dup_f32x2(b0.w);
            bb[4] = dup_f32x2(b1.x); bb[5] = dup_f32x2(b1.y);
            bb[6] = dup_f32x2(b1.z); bb[7] = dup_f32x2(b1.w);
#pragma unroll
            for (int rp = 0; rp < 4; rp++)
#pragma unroll
                for (int c = 0; c < 8; c++)
                    FMA2(acc[rp][c], a2[rp], bb[c]);
        }
    }

    float b8[8];
#pragma unroll
    for (int c = 0; c < 8; c++) b8[c] = bout[tc * 8 + c];

#pragma unroll
    for (int r = 0; r < 8; r++) {
        const int rp = r >> 1;
        const int hi = r & 1;
        const int row = row0 + tr * 8 + r;
        if (row >= N) continue;
        float o[8];
#pragma unroll
        for (int c = 0; c < 8; c++) {
            F2U64 u; u.u = acc[rp][c];
            o[c] = (hi ? u.f.y : u.f.x) + b8[c];
        }
        float4* dst4 = (float4*)&out[row * 64 + tc * 8];
        dst4[0] = make_float4(o[0], o[1], o[2], o[3]);
        dst4[1] = make_float4(o[4], o[5], o[6], o[7]);
    }
}

// ---------------------------------------------------------------------------
extern "C" void kernel_launch(void* const* d_in, const int* in_sizes, int n_in,
                              void* d_out, int out_size)
{
    const float* x    = (const float*)d_in[0];
    const int*   ei   = (const int*)d_in[1];
    const float* Wlin = (const float*)d_in[2];
    const float* att  = (const float*)d_in[3];
    const float* Wout = (const float*)d_in[4];
    const float* bout = (const float*)d_in[5];
    float* out = (float*)d_out;

    const int N = in_sizes[0] / 128;
    const int E = in_sizes[1] / 2;
    const int nb = (N + CHUNK - 1) / CHUNK;

    // One-time resource init (no device memory involved; work per call is
    // identical every call).
    static cudaStream_t sB = nullptr;
    static cudaEvent_t evFork = nullptr, evJoin = nullptr;
    if (sB == nullptr) {
        cudaStreamCreateWithFlags(&sB, cudaStreamNonBlocking);
        cudaEventCreateWithFlags(&evFork, cudaEventDisableTiming);
        cudaEventCreateWithFlags(&evJoin, cudaEventDisableTiming);
    }

    if (sB != nullptr) {
        // fork: CSR build on sB, input GEMM on the capture stream
        cudaEventRecord(evFork, 0);
        cudaStreamWaitEvent(sB, evFork, 0);

        zero_cnt<<<(N / 4 + 255) / 256 + 1, 256, 0, sB>>>(N);
        hist_kernel<<<(E / 4 + 255) / 256 + 1, 256, 0, sB>>>(ei, E);
        scan_phase1<<<nb, 256, 0, sB>>>(N);
        scan_phase3<<<nb, 256, 0, sB>>>(N, E, nb);
        scatter_kernel<<<(E / 4 + 255) / 256 + 1, 256, 0, sB>>>(ei, E);
        cudaEventRecord(evJoin, sB);

        gemm_h_kernel<<<(N + 127) / 128, 128>>>(x, Wlin, att, N);

        // join
        cudaStreamWaitEvent(0, evJoin, 0);
    } else {
        // fallback: serial on the capture stream
        zero_cnt<<<(N / 4 + 255) / 256 + 1, 256>>>(N);
        gemm_h_kernel<<<(N + 127) / 128, 128>>>(x, Wlin, att, N);
        hist_kernel<<<(E / 4 + 255) / 256 + 1, 256>>>(ei, E);
        scan_phase1<<<nb, 256>>>(N);
        scan_phase3<<<nb, 256>>>(N, E, nb);
        scatter_kernel<<<(E / 4 + 255) / 256 + 1, 256>>>(ei, E);
    }

    agg_kernel<<<(N * 32 + 255) / 256, 256>>>(N);
    gemm_out_kernel<<<(N + 127) / 128, 128>>>(Wout, bout, out, N);
}

// round 7
// speedup vs baseline: 1.5639x; 1.1044x over previous
#include <cuda_runtime.h>
#include <cuda_fp16.h>
#include <cuda_bf16.h>
#include <cstdint>

// ---------------------------------------------------------------------------
// SimpleGAT on GB300 (sm_103a) — round 7: K1 on HMMA (mma.sync m16n8k16).
//  tcgen05 is unavailable (harness PTX stage targets compute_103, no 'a'),
//  so K1 uses base-PTX warp MMA: fp16 inputs, fp32 accumulate, ldmatrix from
//  272B-stride SMEM (conflict-free). Epilogue fuses s/d att projections and
//  the fp16 h store.
//  * CSR build forked onto stream B, overlapped with K1; join before agg.
//  * agg: CSR-by-dst register aggregation, fused denominator; global-max
//    softmax stabilization skipped (cancels up to the 1e-9 eps).
//  * K4: f32x2 packed-FMA GEMM.
// ---------------------------------------------------------------------------

#define N_MAX 100000
#define E_MAX 1600000
#define CHUNK 1024
#define NPART 128

__device__ __half2 g_hh[N_MAX * 32];   // h as half2, row = 32 half2 = 128B
__device__ float g_s[N_MAX];
__device__ float g_d[N_MAX];
__device__ float g_agg[N_MAX * 64];
__device__ int   g_cnt[N_MAX];
__device__ int   g_off[N_MAX + 1];
__device__ int   g_cur[N_MAX];
__device__ int   g_srcSorted[E_MAX];
__device__ int   g_part[NPART];

#define FMA2(d, a, b) \
    asm("fma.rn.f32x2 %0, %1, %2, %3;" : "=l"(d) : "l"(a), "l"(b), "l"(d))

__device__ __forceinline__ unsigned long long dup_f32x2(float v)
{
    unsigned long long r;
    asm("mov.b64 %0, {%1, %1};" : "=l"(r) : "r"(__float_as_uint(v)));
    return r;
}

union F2U64 {
    unsigned long long u;
    float2 f;
};

__device__ __forceinline__ uint32_t smem_u32(const void* p)
{
    uint32_t a;
    asm("{ .reg .u64 t; cvta.to.shared.u64 t, %1; cvt.u32.u64 %0, t; }"
        : "=r"(a) : "l"(p));
    return a;
}

// ------------------------- K1: HMMA input GEMM + att proj ------------------
// Block: 256 threads (8 warps), tile 128 rows x 64 cols, K=128.
// Warp w computes rows [w*16, w*16+16) x 64 cols via mma.sync m16n8k16.
// SMEM: A = x tile fp16 [128][128] stride 272B; B = Wlin fp16 [64][128] 272B.
#define K1_STRIDE 272
#define K1_SMA 0
#define K1_SMB (128 * K1_STRIDE)
#define K1_SMEM_TOTAL (128 * K1_STRIDE + 64 * K1_STRIDE)

__global__ __launch_bounds__(256) void gemm_h_hmma(
    const float* __restrict__ x, const float* __restrict__ Wlin,
    const float* __restrict__ att, int N)
{
    extern __shared__ char smem[];
    const uint32_t smem_base = smem_u32(smem);
    const int tid  = threadIdx.x;
    const int wid  = tid >> 5;
    const int lane = tid & 31;
    const int row0 = blockIdx.x * 128;

    // ---- load x tile (fp32 -> fp16), 2 threads per row ----
    {
        const int row  = tid >> 1;
        const int half = tid & 1;          // k 0-63 or 64-127
        const int grow = row0 + row;
        char* dst = smem + K1_SMA + row * K1_STRIDE + half * 128;
        if (grow < N) {
            const float4* srcp = (const float4*)&x[(size_t)grow * 128 + half * 64];
#pragma unroll
            for (int j = 0; j < 8; j++) {
                const float4 v0 = srcp[2 * j];
                const float4 v1 = srcp[2 * j + 1];
                __half2 p[4];
                p[0] = __floats2half2_rn(v0.x, v0.y);
                p[1] = __floats2half2_rn(v0.z, v0.w);
                p[2] = __floats2half2_rn(v1.x, v1.y);
                p[3] = __floats2half2_rn(v1.z, v1.w);
                *(uint4*)(dst + j * 16) = *(uint4*)p;
            }
        } else {
            const uint4 z = make_uint4(0u, 0u, 0u, 0u);
#pragma unroll
            for (int j = 0; j < 8; j++)
                *(uint4*)(dst + j * 16) = z;
        }
    }

    // ---- load Wlin (64x128 fp32 -> fp16), 4 threads per row ----
    {
        const int row = tid >> 2;
        const int q   = tid & 3;           // 32-col quarter
        char* dst = smem + K1_SMB + row * K1_STRIDE + q * 64;
        const float4* srcp = (const float4*)&Wlin[(size_t)row * 128 + q * 32];
#pragma unroll
        for (int j = 0; j < 4; j++) {
            const float4 v0 = srcp[2 * j];
            const float4 v1 = srcp[2 * j + 1];
            __half2 p[4];
            p[0] = __floats2half2_rn(v0.x, v0.y);
            p[1] = __floats2half2_rn(v0.z, v0.w);
            p[2] = __floats2half2_rn(v1.x, v1.y);
            p[3] = __floats2half2_rn(v1.z, v1.w);
            *(uint4*)(dst + j * 16) = *(uint4*)p;
        }
    }
    __syncthreads();

    // ---- mainloop: 8 k-steps of 16, 8 n-tiles of 8 ----
    float acc[8][4];
#pragma unroll
    for (int nt = 0; nt < 8; nt++)
#pragma unroll
        for (int i = 0; i < 4; i++) acc[nt][i] = 0.f;

    // A ldmatrix address (per warp): row = w*16 + lane%16, k-half = lane/16
    const uint32_t aAddrBase = smem_base + K1_SMA +
        (wid * 16 + (lane & 15)) * K1_STRIDE + (lane >> 4) * 16;
    // B ldmatrix address: group = lane/8, li = lane%8
    //   n = nt2*16 + (group/2)*8 + li ; k byte = ks*32 + (group&1)*16
    const int grp = lane >> 3;
    const int li  = lane & 7;
    const uint32_t bAddrBase = smem_base + K1_SMB +
        ((grp >> 1) * 8 + li) * K1_STRIDE + (grp & 1) * 16;

#pragma unroll
    for (int ks = 0; ks < 8; ks++) {
        uint32_t a0, a1, a2, a3;
        asm volatile(
            "ldmatrix.sync.aligned.m8n8.x4.shared.b16 {%0,%1,%2,%3}, [%4];"
            : "=r"(a0), "=r"(a1), "=r"(a2), "=r"(a3)
            : "r"(aAddrBase + ks * 32));
#pragma unroll
        for (int nt2 = 0; nt2 < 4; nt2++) {
            uint32_t b0, b1, b2, b3;
            asm volatile(
                "ldmatrix.sync.aligned.m8n8.x4.shared.b16 {%0,%1,%2,%3}, [%4];"
                : "=r"(b0), "=r"(b1), "=r"(b2), "=r"(b3)
                : "r"(bAddrBase + nt2 * 16 * K1_STRIDE + ks * 32));
            float* c0 = acc[nt2 * 2];
            float* c1 = acc[nt2 * 2 + 1];
            asm volatile(
                "mma.sync.aligned.m16n8k16.row.col.f32.f16.f16.f32 "
                "{%0,%1,%2,%3}, {%4,%5,%6,%7}, {%8,%9}, {%0,%1,%2,%3};"
                : "+f"(c0[0]), "+f"(c0[1]), "+f"(c0[2]), "+f"(c0[3])
                : "r"(a0), "r"(a1), "r"(a2), "r"(a3), "r"(b0), "r"(b1));
            asm volatile(
                "mma.sync.aligned.m16n8k16.row.col.f32.f16.f16.f32 "
                "{%0,%1,%2,%3}, {%4,%5,%6,%7}, {%8,%9}, {%0,%1,%2,%3};"
                : "+f"(c1[0]), "+f"(c1[1]), "+f"(c1[2]), "+f"(c1[3])
                : "r"(a0), "r"(a1), "r"(a2), "r"(a3), "r"(b2), "r"(b3));
        }
    }

    // ---- epilogue: h (fp16) store + fused s/d projections ----
    // D fragment: d0,d1 -> row lane/4, cols nt*8+(lane%3)*2... cols nt*8+(lane&3)*2+{0,1}
    //             d2,d3 -> row lane/4+8, same cols
    float2 aS[8], aD[8];
#pragma unroll
    for (int nt = 0; nt < 8; nt++) {
        const int col = nt * 8 + (lane & 3) * 2;
        aS[nt] = *(const float2*)&att[col];
        aD[nt] = *(const float2*)&att[64 + col];
    }

#pragma unroll
    for (int r = 0; r < 2; r++) {
        const int rowg = row0 + wid * 16 + (lane >> 2) + r * 8;
        const bool ok = (rowg < N);
        float sp = 0.f, dp = 0.f;
#pragma unroll
        for (int nt = 0; nt < 8; nt++) {
            const float c0 = acc[nt][r * 2 + 0];
            const float c1 = acc[nt][r * 2 + 1];
            sp += c0 * aS[nt].x + c1 * aS[nt].y;
            dp += c0 * aD[nt].x + c1 * aD[nt].y;
            if (ok)
                g_hh[(size_t)rowg * 32 + nt * 4 + (lane & 3)] =
                    __floats2half2_rn(c0, c1);
        }
        sp += __shfl_xor_sync(0xffffffffu, sp, 1);
        sp += __shfl_xor_sync(0xffffffffu, sp, 2);
        dp += __shfl_xor_sync(0xffffffffu, dp, 1);
        dp += __shfl_xor_sync(0xffffffffu, dp, 2);
        if ((lane & 3) == 0 && ok) {
            g_s[rowg] = sp;
            g_d[rowg] = dp;
        }
    }
}

// ------------------------- Z: zero counts (stream B head) ------------------
__global__ __launch_bounds__(256) void zero_cnt(int N)
{
    const int i = blockIdx.x * blockDim.x + threadIdx.x;
    const int i4 = i * 4;
    if (i4 + 3 < N) {
        *(int4*)&g_cnt[i4] = make_int4(0, 0, 0, 0);
    } else {
        for (int j = 0; j < 4; j++)
            if (i4 + j < N) g_cnt[i4 + j] = 0;
    }
}

// ------------------------- H: histogram (4 edges/thread) -------------------
__global__ __launch_bounds__(256) void hist_kernel(const int* __restrict__ ei, int E)
{
    const int t = blockIdx.x * blockDim.x + threadIdx.x;
    const int e4 = t * 4;
    if (e4 + 3 < E) {
        const int4 d = *(const int4*)&ei[E + e4];
        atomicAdd(&g_cnt[d.x], 1);
        atomicAdd(&g_cnt[d.y], 1);
        atomicAdd(&g_cnt[d.z], 1);
        atomicAdd(&g_cnt[d.w], 1);
    } else {
        for (int j = 0; j < 4; j++)
            if (e4 + j < E) atomicAdd(&g_cnt[ei[E + e4 + j]], 1);
    }
}

// ------------------------- S1: per-chunk totals ----------------------------
__global__ __launch_bounds__(256) void scan_phase1(int N)
{
    const int base = blockIdx.x * CHUNK;
    const int t = threadIdx.x;
    const int idx = base + t * 4;
    int sum = 0;
    if (idx + 3 < N) {
        const int4 v = *(const int4*)&g_cnt[idx];
        sum = v.x + v.y + v.z + v.w;
    } else {
#pragma unroll
        for (int i = 0; i < 4; i++)
            if (idx + i < N) sum += g_cnt[idx + i];
    }
    __shared__ int warpS[8];
#pragma unroll
    for (int m = 16; m >= 1; m >>= 1) sum += __shfl_xor_sync(0xffffffffu, sum, m);
    if ((t & 31) == 0) warpS[t >> 5] = sum;
    __syncthreads();
    if (t == 0) {
        int s = 0;
#pragma unroll
        for (int i = 0; i < 8; i++) s += warpS[i];
        g_part[blockIdx.x] = s;
    }
}

// ------------------------- S3: exclusive scan ------------------------------
__global__ __launch_bounds__(256) void scan_phase3(int N, int E, int nb)
{
    const int t = threadIdx.x;

    __shared__ int psm[NPART];
    if (t < NPART) psm[t] = (t < nb) ? g_part[t] : 0;
    __syncthreads();
    for (int off = 1; off < NPART; off <<= 1) {
        int add = 0;
        if (t < NPART && t >= off) add = psm[t - off];
        __syncthreads();
        if (t < NPART) psm[t] += add;
        __syncthreads();
    }
    const int chunkBase = (blockIdx.x == 0) ? 0 : psm[blockIdx.x - 1];

    const int base = blockIdx.x * CHUNK;
    const int idx0 = base + t * 4;
    int v[4];
#pragma unroll
    for (int i = 0; i < 4; i++) {
        const int idx = idx0 + i;
        v[i] = (idx < N) ? g_cnt[idx] : 0;
    }
    const int tsum = v[0] + v[1] + v[2] + v[3];

    __shared__ int sm[256];
    sm[t] = tsum;
    __syncthreads();
    for (int off = 1; off < 256; off <<= 1) {
        const int add = (t >= off) ? sm[t - off] : 0;
        __syncthreads();
        sm[t] += add;
        __syncthreads();
    }
    int run = sm[t] - tsum + chunkBase;
#pragma unroll
    for (int i = 0; i < 4; i++) {
        const int idx = idx0 + i;
        if (idx < N) {
            g_off[idx] = run;
            g_cur[idx] = run;
            run += v[i];
        }
    }
    if (blockIdx.x == 0 && t == 0) g_off[N] = E;
}

// ------------------------- SC: scatter src into CSR ------------------------
__global__ __launch_bounds__(256) void scatter_kernel(const int* __restrict__ ei, int E)
{
    const int t = blockIdx.x * blockDim.x + threadIdx.x;
    const int e4 = t * 4;
    if (e4 + 3 < E) {
        const int4 s = *(const int4*)&ei[e4];
        const int4 d = *(const int4*)&ei[E + e4];
        g_srcSorted[atomicAdd(&g_cur[d.x], 1)] = s.x;
        g_srcSorted[atomicAdd(&g_cur[d.y], 1)] = s.y;
        g_srcSorted[atomicAdd(&g_cur[d.z], 1)] = s.z;
        g_srcSorted[atomicAdd(&g_cur[d.w], 1)] = s.w;
    } else {
        for (int j = 0; j < 4; j++) {
            const int e = e4 + j;
            if (e < E)
                g_srcSorted[atomicAdd(&g_cur[ei[E + e]], 1)] = ei[e];
        }
    }
}

// ------------------------- AG: register aggregation ------------------------
__global__ __launch_bounds__(256) void agg_kernel(int N)
{
    const int warp = (blockIdx.x * blockDim.x + threadIdx.x) >> 5;
    if (warp >= N) return;
    const int lane = threadIdx.x & 31;
    const int part = lane & 7;
    const int sub  = lane >> 3;

    const int start = g_off[warp];
    const int end   = g_off[warp + 1];
    const float dnode = g_d[warp];

    unsigned long long acc2[4] = {0ull, 0ull, 0ull, 0ull};
    float wsum = 0.f;

    const int cnt = end - start;
    const int iters = (cnt + 3) >> 2;
    for (int it = 0; it < iters; ++it) {
        const int e = start + it * 4 + sub;
        const bool valid = (e < end);
        const int src = g_srcSorted[valid ? e : 0];
        float ev = g_s[src] + dnode;
        ev = (ev > 0.f) ? ev : 0.2f * ev;
        const float w = valid ? __expf(ev) : 0.f;
        if (part == 0) wsum += w;
        const unsigned long long w2 = dup_f32x2(w);
        const uint4 hvu = *(const uint4*)(((const char*)g_hh) + ((size_t)src * 128 + part * 16));
        const __half2* hp = (const __half2*)&hvu;
#pragma unroll
        for (int j = 0; j < 4; j++) {
            F2U64 hf; hf.f = __half22float2(hp[j]);
            FMA2(acc2[j], hf.u, w2);
        }
    }

#pragma unroll
    for (int j = 0; j < 4; j++) {
        F2U64 a; a.u = acc2[j];
        a.f.x += __shfl_xor_sync(0xffffffffu, a.f.x, 8);
        a.f.y += __shfl_xor_sync(0xffffffffu, a.f.y, 8);
        a.f.x += __shfl_xor_sync(0xffffffffu, a.f.x, 16);
        a.f.y += __shfl_xor_sync(0xffffffffu, a.f.y, 16);
        acc2[j] = a.u;
    }
    wsum += __shfl_xor_sync(0xffffffffu, wsum, 8);
    wsum += __shfl_xor_sync(0xffffffffu, wsum, 16);
    const float den = __shfl_sync(0xffffffffu, wsum, 0) + 1e-9f;

    if (sub == 0) {
        const float inv = 1.f / den;
        float o[8];
#pragma unroll
        for (int j = 0; j < 4; j++) {
            F2U64 a; a.u = acc2[j];
            o[2 * j]     = fmaxf(a.f.x * inv, 0.f);
            o[2 * j + 1] = fmaxf(a.f.y * inv, 0.f);
        }
        float4* dst4 = (float4*)&g_agg[warp * 64 + part * 8];
        dst4[0] = make_float4(o[0], o[1], o[2], o[3]);
        dst4[1] = make_float4(o[4], o[5], o[6], o[7]);
    }
}

// ------------------------- K4: output GEMM (f32x2) -------------------------
__global__ __launch_bounds__(128) void gemm_out_kernel(
    const float* __restrict__ Wout, const float* __restrict__ bout,
    float* __restrict__ out, int N)
{
    __shared__ float As[16][128];
    __shared__ float Bs[16][64];

    const int tid = threadIdx.x;
    const int tc  = tid & 7;
    const int tr  = tid >> 3;
    const int row0 = blockIdx.x * 128;

    unsigned long long acc[4][8];
#pragma unroll
    for (int rp = 0; rp < 4; rp++)
#pragma unroll
        for (int c = 0; c < 8; c++) acc[rp][c] = 0ull;

    const int arow = row0 + tid;
    const int wrow = tid >> 1;
    const int wq0  = (tid & 1) * 2;

    for (int k0 = 0; k0 < 64; k0 += 16) {
        __syncthreads();
#pragma unroll
        for (int q = 0; q < 4; q++) {
            float4 v = make_float4(0.f, 0.f, 0.f, 0.f);
            if (arow < N) v = *(const float4*)&g_agg[arow * 64 + k0 + q * 4];
            As[q * 4 + 0][tid] = v.x;
            As[q * 4 + 1][tid] = v.y;
            As[q * 4 + 2][tid] = v.z;
            As[q * 4 + 3][tid] = v.w;
        }
#pragma unroll
        for (int qi = 0; qi < 2; qi++) {
            const int q = wq0 + qi;
            const float4 w = *(const float4*)&Wout[wrow * 64 + k0 + q * 4];
            Bs[q * 4 + 0][wrow] = w.x;
            Bs[q * 4 + 1][wrow] = w.y;
            Bs[q * 4 + 2][wrow] = w.z;
            Bs[q * 4 + 3][wrow] = w.w;
        }
        __syncthreads();

#pragma unroll
        for (int kk = 0; kk < 16; kk++) {
            const ulonglong2 aA = *(const ulonglong2*)&As[kk][tr * 8];
            const ulonglong2 aB = *(const ulonglong2*)&As[kk][tr * 8 + 4];
            unsigned long long a2[4] = { aA.x, aA.y, aB.x, aB.y };
            const float4 b0 = *(const float4*)&Bs[kk][tc * 8];
            const float4 b1 = *(const float4*)&Bs[kk][tc * 8 + 4];
            unsigned long long bb[8];
            bb[0] = dup_f32x2(b0.x); bb[1] = dup_f32x2(b0.y);
            bb[2] = dup_f32x2(b0.z); bb[3] = dup_f32x2(b0.w);
            bb[4] = dup_f32x2(b1.x); bb[5] = dup_f32x2(b1.y);
            bb[6] = dup_f32x2(b1.z); bb[7] = dup_f32x2(b1.w);
#pragma unroll
            for (int rp = 0; rp < 4; rp++)
#pragma unroll
                for (int c = 0; c < 8; c++)
                    FMA2(acc[rp][c], a2[rp], bb[c]);
        }
    }

    float b8[8];
#pragma unroll
    for (int c = 0; c < 8; c++) b8[c] = bout[tc * 8 + c];

#pragma unroll
    for (int r = 0; r < 8; r++) {
        const int rp = r >> 1;
        const int hi = r & 1;
        const int row = row0 + tr * 8 + r;
        if (row >= N) continue;
        float o[8];
#pragma unroll
        for (int c = 0; c < 8; c++) {
            F2U64 u; u.u = acc[rp][c];
            o[c] = (hi ? u.f.y : u.f.x) + b8[c];
        }
        float4* dst4 = (float4*)&out[row * 64 + tc * 8];
        dst4[0] = make_float4(o[0], o[1], o[2], o[3]);
        dst4[1] = make_float4(o[4], o[5], o[6], o[7]);
    }
}

// ---------------------------------------------------------------------------
extern "C" void kernel_launch(void* const* d_in, const int* in_sizes, int n_in,
                              void* d_out, int out_size)
{
    const float* x    = (const float*)d_in[0];
    const int*   ei   = (const int*)d_in[1];
    const float* Wlin = (const float*)d_in[2];
    const float* att  = (const float*)d_in[3];
    const float* Wout = (const float*)d_in[4];
    const float* bout = (const float*)d_in[5];
    float* out = (float*)d_out;

    const int N = in_sizes[0] / 128;
    const int E = in_sizes[1] / 2;
    const int nb = (N + CHUNK - 1) / CHUNK;

    static cudaStream_t sB = nullptr;
    static cudaEvent_t evFork = nullptr, evJoin = nullptr;
    static bool attrSet = false;
    if (sB == nullptr) {
        cudaStreamCreateWithFlags(&sB, cudaStreamNonBlocking);
        cudaEventCreateWithFlags(&evFork, cudaEventDisableTiming);
        cudaEventCreateWithFlags(&evJoin, cudaEventDisableTiming);
    }
    if (!attrSet) {
        cudaFuncSetAttribute(gemm_h_hmma,
                             cudaFuncAttributeMaxDynamicSharedMemorySize,
                             K1_SMEM_TOTAL);
        attrSet = true;
    }

    if (sB != nullptr) {
        cudaEventRecord(evFork, 0);
        cudaStreamWaitEvent(sB, evFork, 0);

        zero_cnt<<<(N / 4 + 255) / 256 + 1, 256, 0, sB>>>(N);
        hist_kernel<<<(E / 4 + 255) / 256 + 1, 256, 0, sB>>>(ei, E);
        scan_phase1<<<nb, 256, 0, sB>>>(N);
        scan_phase3<<<nb, 256, 0, sB>>>(N, E, nb);
        scatter_kernel<<<(E / 4 + 255) / 256 + 1, 256, 0, sB>>>(ei, E);
        cudaEventRecord(evJoin, sB);

        gemm_h_hmma<<<(N + 127) / 128, 256, K1_SMEM_TOTAL>>>(x, Wlin, att, N);

        cudaStreamWaitEvent(0, evJoin, 0);
    } else {
        zero_cnt<<<(N / 4 + 255) / 256 + 1, 256>>>(N);
        gemm_h_hmma<<<(N + 127) / 128, 256, K1_SMEM_TOTAL>>>(x, Wlin, att, N);
        hist_kernel<<<(E / 4 + 255) / 256 + 1, 256>>>(ei, E);
        scan_phase1<<<nb, 256>>>(N);
        scan_phase3<<<nb, 256>>>(N, E, nb);
        scatter_kernel<<<(E / 4 + 255) / 256 + 1, 256>>>(ei, E);
    }

    agg_kernel<<<(N * 32 + 255) / 256, 256>>>(N);
    gemm_out_kernel<<<(N + 127) / 128, 128>>>(Wout, bout, out, N);
}

// round 8
// speedup vs baseline: 1.8926x; 1.2102x over previous
#include <cuda_runtime.h>
#include <cuda_fp16.h>
#include <cuda_bf16.h>
#include <cstdint>

// ---------------------------------------------------------------------------
// SimpleGAT on GB300 (sm_103a) — round 8:
//  * K1 and K4 both on HMMA (mma.sync m16n8k16, fp16 in / fp32 accum).
//  * agg output stored fp16 (g_aggh) -> K4 reads fp16 directly.
//  * CSR scan collapsed to ONE kernel (decoupled lookback, all blocks
//    wave-1 resident so parallel partial-lookback is deadlock-free).
//  * CSR build forked onto stream B, overlapped with K1; join before agg.
//  * global-max softmax stabilization skipped (cancels up to the 1e-9 eps).
// ---------------------------------------------------------------------------

#define N_MAX 100000
#define E_MAX 1600000
#define CHUNK 1024
#define NPART 128

__device__ __half2 g_hh[N_MAX * 32];    // h as half2, row = 32 half2 = 128B
__device__ __half2 g_aggh[N_MAX * 32];  // relu(agg) as half2
__device__ float g_s[N_MAX];
__device__ float g_d[N_MAX];
__device__ int   g_cnt[N_MAX];
__device__ int   g_off[N_MAX + 1];
__device__ int   g_cur[N_MAX];
__device__ int   g_srcSorted[E_MAX];
__device__ unsigned long long g_state[NPART];   // scan lookback state

#define FMA2(d, a, b) \
    asm("fma.rn.f32x2 %0, %1, %2, %3;" : "=l"(d) : "l"(a), "l"(b), "l"(d))

__device__ __forceinline__ unsigned long long dup_f32x2(float v)
{
    unsigned long long r;
    asm("mov.b64 %0, {%1, %1};" : "=l"(r) : "r"(__float_as_uint(v)));
    return r;
}

union F2U64 {
    unsigned long long u;
    float2 f;
};

__device__ __forceinline__ uint32_t smem_u32(const void* p)
{
    uint32_t a;
    asm("{ .reg .u64 t; cvta.to.shared.u64 t, %1; cvt.u32.u64 %0, t; }"
        : "=r"(a) : "l"(p));
    return a;
}

// ------------------------- K1: HMMA input GEMM + att proj ------------------
#define K1_STRIDE 272
#define K1_SMA 0
#define K1_SMB (128 * K1_STRIDE)
#define K1_SMEM_TOTAL (128 * K1_STRIDE + 64 * K1_STRIDE)

__global__ __launch_bounds__(256) void gemm_h_hmma(
    const float* __restrict__ x, const float* __restrict__ Wlin,
    const float* __restrict__ att, int N)
{
    extern __shared__ char smem[];
    const uint32_t smem_base = smem_u32(smem);
    const int tid  = threadIdx.x;
    const int wid  = tid >> 5;
    const int lane = tid & 31;
    const int row0 = blockIdx.x * 128;

    // ---- load x tile (fp32 -> fp16), 2 threads per row ----
    {
        const int row  = tid >> 1;
        const int half = tid & 1;
        const int grow = row0 + row;
        char* dst = smem + K1_SMA + row * K1_STRIDE + half * 128;
        if (grow < N) {
            const float4* srcp = (const float4*)&x[(size_t)grow * 128 + half * 64];
#pragma unroll
            for (int j = 0; j < 8; j++) {
                const float4 v0 = srcp[2 * j];
                const float4 v1 = srcp[2 * j + 1];
                __half2 p[4];
                p[0] = __floats2half2_rn(v0.x, v0.y);
                p[1] = __floats2half2_rn(v0.z, v0.w);
                p[2] = __floats2half2_rn(v1.x, v1.y);
                p[3] = __floats2half2_rn(v1.z, v1.w);
                *(uint4*)(dst + j * 16) = *(uint4*)p;
            }
        } else {
            const uint4 z = make_uint4(0u, 0u, 0u, 0u);
#pragma unroll
            for (int j = 0; j < 8; j++)
                *(uint4*)(dst + j * 16) = z;
        }
    }

    // ---- load Wlin (64x128 fp32 -> fp16), 4 threads per row ----
    {
        const int row = tid >> 2;
        const int q   = tid & 3;
        char* dst = smem + K1_SMB + row * K1_STRIDE + q * 64;
        const float4* srcp = (const float4*)&Wlin[(size_t)row * 128 + q * 32];
#pragma unroll
        for (int j = 0; j < 4; j++) {
            const float4 v0 = srcp[2 * j];
            const float4 v1 = srcp[2 * j + 1];
            __half2 p[4];
            p[0] = __floats2half2_rn(v0.x, v0.y);
            p[1] = __floats2half2_rn(v0.z, v0.w);
            p[2] = __floats2half2_rn(v1.x, v1.y);
            p[3] = __floats2half2_rn(v1.z, v1.w);
            *(uint4*)(dst + j * 16) = *(uint4*)p;
        }
    }
    __syncthreads();

    float acc[8][4];
#pragma unroll
    for (int nt = 0; nt < 8; nt++)
#pragma unroll
        for (int i = 0; i < 4; i++) acc[nt][i] = 0.f;

    const uint32_t aAddrBase = smem_base + K1_SMA +
        (wid * 16 + (lane & 15)) * K1_STRIDE + (lane >> 4) * 16;
    const int grp = lane >> 3;
    const int li  = lane & 7;
    const uint32_t bAddrBase = smem_base + K1_SMB +
        ((grp >> 1) * 8 + li) * K1_STRIDE + (grp & 1) * 16;

#pragma unroll
    for (int ks = 0; ks < 8; ks++) {
        uint32_t a0, a1, a2, a3;
        asm volatile(
            "ldmatrix.sync.aligned.m8n8.x4.shared.b16 {%0,%1,%2,%3}, [%4];"
            : "=r"(a0), "=r"(a1), "=r"(a2), "=r"(a3)
            : "r"(aAddrBase + ks * 32));
#pragma unroll
        for (int nt2 = 0; nt2 < 4; nt2++) {
            uint32_t b0, b1, b2, b3;
            asm volatile(
                "ldmatrix.sync.aligned.m8n8.x4.shared.b16 {%0,%1,%2,%3}, [%4];"
                : "=r"(b0), "=r"(b1), "=r"(b2), "=r"(b3)
                : "r"(bAddrBase + nt2 * 16 * K1_STRIDE + ks * 32));
            float* c0 = acc[nt2 * 2];
            float* c1 = acc[nt2 * 2 + 1];
            asm volatile(
                "mma.sync.aligned.m16n8k16.row.col.f32.f16.f16.f32 "
                "{%0,%1,%2,%3}, {%4,%5,%6,%7}, {%8,%9}, {%0,%1,%2,%3};"
                : "+f"(c0[0]), "+f"(c0[1]), "+f"(c0[2]), "+f"(c0[3])
                : "r"(a0), "r"(a1), "r"(a2), "r"(a3), "r"(b0), "r"(b1));
            asm volatile(
                "mma.sync.aligned.m16n8k16.row.col.f32.f16.f16.f32 "
                "{%0,%1,%2,%3}, {%4,%5,%6,%7}, {%8,%9}, {%0,%1,%2,%3};"
                : "+f"(c1[0]), "+f"(c1[1]), "+f"(c1[2]), "+f"(c1[3])
                : "r"(a0), "r"(a1), "r"(a2), "r"(a3), "r"(b2), "r"(b3));
        }
    }

    float2 aS[8], aD[8];
#pragma unroll
    for (int nt = 0; nt < 8; nt++) {
        const int col = nt * 8 + (lane & 3) * 2;
        aS[nt] = *(const float2*)&att[col];
        aD[nt] = *(const float2*)&att[64 + col];
    }

#pragma unroll
    for (int r = 0; r < 2; r++) {
        const int rowg = row0 + wid * 16 + (lane >> 2) + r * 8;
        const bool ok = (rowg < N);
        float sp = 0.f, dp = 0.f;
#pragma unroll
        for (int nt = 0; nt < 8; nt++) {
            const float c0 = acc[nt][r * 2 + 0];
            const float c1 = acc[nt][r * 2 + 1];
            sp += c0 * aS[nt].x + c1 * aS[nt].y;
            dp += c0 * aD[nt].x + c1 * aD[nt].y;
            if (ok)
                g_hh[(size_t)rowg * 32 + nt * 4 + (lane & 3)] =
                    __floats2half2_rn(c0, c1);
        }
        sp += __shfl_xor_sync(0xffffffffu, sp, 1);
        sp += __shfl_xor_sync(0xffffffffu, sp, 2);
        dp += __shfl_xor_sync(0xffffffffu, dp, 1);
        dp += __shfl_xor_sync(0xffffffffu, dp, 2);
        if ((lane & 3) == 0 && ok) {
            g_s[rowg] = sp;
            g_d[rowg] = dp;
        }
    }
}

// ------------------------- Z: zero counts + scan state ---------------------
__global__ __launch_bounds__(256) void zero_cnt(int N)
{
    const int i = blockIdx.x * blockDim.x + threadIdx.x;
    const int i4 = i * 4;
    if (i4 + 3 < N) {
        *(int4*)&g_cnt[i4] = make_int4(0, 0, 0, 0);
    } else {
        for (int j = 0; j < 4; j++)
            if (i4 + j < N) g_cnt[i4 + j] = 0;
    }
    if (i < NPART) g_state[i] = 0ull;
}

// ------------------------- H: histogram ------------------------------------
__global__ __launch_bounds__(256) void hist_kernel(const int* __restrict__ ei, int E)
{
    const int t = blockIdx.x * blockDim.x + threadIdx.x;
    const int e4 = t * 4;
    if (e4 + 3 < E) {
        const int4 d = *(const int4*)&ei[E + e4];
        atomicAdd(&g_cnt[d.x], 1);
        atomicAdd(&g_cnt[d.y], 1);
        atomicAdd(&g_cnt[d.z], 1);
        atomicAdd(&g_cnt[d.w], 1);
    } else {
        for (int j = 0; j < 4; j++)
            if (e4 + j < E) atomicAdd(&g_cnt[ei[E + e4 + j]], 1);
    }
}

// ------------------------- S: one-launch exclusive scan --------------------
// Grid = nb (<= 98) blocks, all wave-1 resident: decoupled lookback over
// published partials (u64 = flag<<63 | sum) is deadlock-free.
__global__ __launch_bounds__(256) void scan_fused(int N, int E, int nb)
{
    const int b = blockIdx.x;
    const int t = threadIdx.x;
    const int idx0 = b * CHUNK + t * 4;

    int v[4];
#pragma unroll
    for (int i = 0; i < 4; i++) {
        const int idx = idx0 + i;
        v[i] = (idx < N) ? g_cnt[idx] : 0;
    }
    const int tsum = v[0] + v[1] + v[2] + v[3];

    __shared__ int sm[256];
    __shared__ int blockBase;
    sm[t] = tsum;
    __syncthreads();
    for (int off = 1; off < 256; off <<= 1) {
        const int add = (t >= off) ? sm[t - off] : 0;
        __syncthreads();
        sm[t] += add;
        __syncthreads();
    }

    // publish this block's partial sum
    if (t == 0) {
        const unsigned long long pkt =
            (1ull << 63) | (unsigned long long)(unsigned)sm[255];
        __threadfence();
        atomicExch(&g_state[b], pkt);
    }

    // lookback: warp 0 sums all predecessors' partials
    if (t < 32) {
        int sumPrev = 0;
        for (int base = 0; base < b; base += 32) {
            const int i = base + t;
            if (i < b) {
                unsigned long long pkt;
                do {
                    pkt = atomicAdd(&g_state[i], 0ull);
                } while (!(pkt >> 63));
                sumPrev += (int)(unsigned)(pkt & 0xffffffffull);
            }
        }
#pragma unroll
        for (int m = 16; m >= 1; m >>= 1)
            sumPrev += __shfl_xor_sync(0xffffffffu, sumPrev, m);
        if (t == 0) blockBase = sumPrev;
    }
    __syncthreads();

    int run = sm[t] - tsum + blockBase;
#pragma unroll
    for (int i = 0; i < 4; i++) {
        const int idx = idx0 + i;
        if (idx < N) {
            g_off[idx] = run;
            g_cur[idx] = run;
            run += v[i];
        }
    }
    if (b == 0 && t == 0) g_off[N] = E;
}

// ------------------------- SC: scatter src into CSR ------------------------
__global__ __launch_bounds__(256) void scatter_kernel(const int* __restrict__ ei, int E)
{
    const int t = blockIdx.x * blockDim.x + threadIdx.x;
    const int e4 = t * 4;
    if (e4 + 3 < E) {
        const int4 s = *(const int4*)&ei[e4];
        const int4 d = *(const int4*)&ei[E + e4];
        g_srcSorted[atomicAdd(&g_cur[d.x], 1)] = s.x;
        g_srcSorted[atomicAdd(&g_cur[d.y], 1)] = s.y;
        g_srcSorted[atomicAdd(&g_cur[d.z], 1)] = s.z;
        g_srcSorted[atomicAdd(&g_cur[d.w], 1)] = s.w;
    } else {
        for (int j = 0; j < 4; j++) {
            const int e = e4 + j;
            if (e < E)
                g_srcSorted[atomicAdd(&g_cur[ei[E + e]], 1)] = ei[e];
        }
    }
}

// ------------------------- AG: register aggregation ------------------------
__global__ __launch_bounds__(256) void agg_kernel(int N)
{
    const int warp = (blockIdx.x * blockDim.x + threadIdx.x) >> 5;
    if (warp >= N) return;
    const int lane = threadIdx.x & 31;
    const int part = lane & 7;
    const int sub  = lane >> 3;

    const int start = g_off[warp];
    const int end   = g_off[warp + 1];
    const float dnode = g_d[warp];

    unsigned long long acc2[4] = {0ull, 0ull, 0ull, 0ull};
    float wsum = 0.f;

    const int cnt = end - start;
    const int iters = (cnt + 3) >> 2;
    for (int it = 0; it < iters; ++it) {
        const int e = start + it * 4 + sub;
        const bool valid = (e < end);
        const int src = g_srcSorted[valid ? e : 0];
        float ev = g_s[src] + dnode;
        ev = (ev > 0.f) ? ev : 0.2f * ev;
        const float w = valid ? __expf(ev) : 0.f;
        if (part == 0) wsum += w;
        const unsigned long long w2 = dup_f32x2(w);
        const uint4 hvu = *(const uint4*)(((const char*)g_hh) + ((size_t)src * 128 + part * 16));
        const __half2* hp = (const __half2*)&hvu;
#pragma unroll
        for (int j = 0; j < 4; j++) {
            F2U64 hf; hf.f = __half22float2(hp[j]);
            FMA2(acc2[j], hf.u, w2);
        }
    }

#pragma unroll
    for (int j = 0; j < 4; j++) {
        F2U64 a; a.u = acc2[j];
        a.f.x += __shfl_xor_sync(0xffffffffu, a.f.x, 8);
        a.f.y += __shfl_xor_sync(0xffffffffu, a.f.y, 8);
        a.f.x += __shfl_xor_sync(0xffffffffu, a.f.x, 16);
        a.f.y += __shfl_xor_sync(0xffffffffu, a.f.y, 16);
        acc2[j] = a.u;
    }
    wsum += __shfl_xor_sync(0xffffffffu, wsum, 8);
    wsum += __shfl_xor_sync(0xffffffffu, wsum, 16);
    const float den = __shfl_sync(0xffffffffu, wsum, 0) + 1e-9f;

    if (sub == 0) {
        const float inv = 1.f / den;
        __half2 p[4];
#pragma unroll
        for (int j = 0; j < 4; j++) {
            F2U64 a; a.u = acc2[j];
            p[j] = __floats2half2_rn(fmaxf(a.f.x * inv, 0.f),
                                     fmaxf(a.f.y * inv, 0.f));
        }
        *(uint4*)&g_aggh[warp * 32 + part * 4] = *(uint4*)p;
    }
}

// ------------------------- K4: HMMA output GEMM ----------------------------
// out = aggh(fp16) @ Wout^T + b. Tile 128x64, K=64, 8 warps.
#define KO_STRIDE 144
#define KO_SMB (128 * KO_STRIDE)

__global__ __launch_bounds__(256) void gemm_out_hmma(
    const float* __restrict__ Wout, const float* __restrict__ bout,
    float* __restrict__ out, int N)
{
    __shared__ char smem[128 * KO_STRIDE + 64 * KO_STRIDE];
    const uint32_t smem_base = smem_u32(smem);
    const int tid  = threadIdx.x;
    const int wid  = tid >> 5;
    const int lane = tid & 31;
    const int row0 = blockIdx.x * 128;

    // ---- load A from g_aggh (already fp16): 128 rows x 8 x 16B ----
    for (int task = tid; task < 128 * 8; task += 256) {
        const int row = task >> 3;
        const int c   = task & 7;
        const int grow = row0 + row;
        uint4 v = make_uint4(0u, 0u, 0u, 0u);
        if (grow < N) v = *(const uint4*)&g_aggh[(size_t)grow * 32 + c * 4];
        *(uint4*)(smem + row * KO_STRIDE + c * 16) = v;
    }

    // ---- load Wout (64x64 fp32 -> fp16), 4 threads per row (16 cols each) --
    {
        const int row = tid >> 2;
        const int q   = tid & 3;
        const float4* srcp = (const float4*)&Wout[(size_t)row * 64 + q * 16];
        char* dst = smem + KO_SMB + row * KO_STRIDE + q * 32;
#pragma unroll
        for (int j = 0; j < 2; j++) {
            const float4 v0 = srcp[2 * j];
            const float4 v1 = srcp[2 * j + 1];
            __half2 p[4];
            p[0] = __floats2half2_rn(v0.x, v0.y);
            p[1] = __floats2half2_rn(v0.z, v0.w);
            p[2] = __floats2half2_rn(v1.x, v1.y);
            p[3] = __floats2half2_rn(v1.z, v1.w);
            *(uint4*)(dst + j * 16) = *(uint4*)p;
        }
    }
    __syncthreads();

    float acc[8][4];
#pragma unroll
    for (int nt = 0; nt < 8; nt++)
#pragma unroll
        for (int i = 0; i < 4; i++) acc[nt][i] = 0.f;

    const uint32_t aAddrBase = smem_base +
        (wid * 16 + (lane & 15)) * KO_STRIDE + (lane >> 4) * 16;
    const int grp = lane >> 3;
    const int li  = lane & 7;
    const uint32_t bAddrBase = smem_base + KO_SMB +
        ((grp >> 1) * 8 + li) * KO_STRIDE + (grp & 1) * 16;

#pragma unroll
    for (int ks = 0; ks < 4; ks++) {
        uint32_t a0, a1, a2, a3;
        asm volatile(
            "ldmatrix.sync.aligned.m8n8.x4.shared.b16 {%0,%1,%2,%3}, [%4];"
            : "=r"(a0), "=r"(a1), "=r"(a2), "=r"(a3)
            : "r"(aAddrBase + ks * 32));
#pragma unroll
        for (int nt2 = 0; nt2 < 4; nt2++) {
            uint32_t b0, b1, b2, b3;
            asm volatile(
                "ldmatrix.sync.aligned.m8n8.x4.shared.b16 {%0,%1,%2,%3}, [%4];"
                : "=r"(b0), "=r"(b1), "=r"(b2), "=r"(b3)
                : "r"(bAddrBase + nt2 * 16 * KO_STRIDE + ks * 32));
            float* c0 = acc[nt2 * 2];
            float* c1 = acc[nt2 * 2 + 1];
            asm volatile(
                "mma.sync.aligned.m16n8k16.row.col.f32.f16.f16.f32 "
                "{%0,%1,%2,%3}, {%4,%5,%6,%7}, {%8,%9}, {%0,%1,%2,%3};"
                : "+f"(c0[0]), "+f"(c0[1]), "+f"(c0[2]), "+f"(c0[3])
                : "r"(a0), "r"(a1), "r"(a2), "r"(a3), "r"(b0), "r"(b1));
            asm volatile(
                "mma.sync.aligned.m16n8k16.row.col.f32.f16.f16.f32 "
                "{%0,%1,%2,%3}, {%4,%5,%6,%7}, {%8,%9}, {%0,%1,%2,%3};"
                : "+f"(c1[0]), "+f"(c1[1]), "+f"(c1[2]), "+f"(c1[3])
                : "r"(a0), "r"(a1), "r"(a2), "r"(a3), "r"(b2), "r"(b3));
        }
    }

    float2 bias[8];
#pragma unroll
    for (int nt = 0; nt < 8; nt++)
        bias[nt] = *(const float2*)&bout[nt * 8 + (lane & 3) * 2];

#pragma unroll
    for (int r = 0; r < 2; r++) {
        const int rowg = row0 + wid * 16 + (lane >> 2) + r * 8;
        if (rowg >= N) continue;
#pragma unroll
        for (int nt = 0; nt < 8; nt++) {
            const int col = nt * 8 + (lane & 3) * 2;
            float2 o;
            o.x = acc[nt][r * 2 + 0] + bias[nt].x;
            o.y = acc[nt][r * 2 + 1] + bias[nt].y;
            *(float2*)&out[(size_t)rowg * 64 + col] = o;
        }
    }
}

// ---------------------------------------------------------------------------
extern "C" void kernel_launch(void* const* d_in, const int* in_sizes, int n_in,
                              void* d_out, int out_size)
{
    const float* x    = (const float*)d_in[0];
    const int*   ei   = (const int*)d_in[1];
    const float* Wlin = (const float*)d_in[2];
    const float* att  = (const float*)d_in[3];
    const float* Wout = (const float*)d_in[4];
    const float* bout = (const float*)d_in[5];
    float* out = (float*)d_out;

    const int N = in_sizes[0] / 128;
    const int E = in_sizes[1] / 2;
    const int nb = (N + CHUNK - 1) / CHUNK;

    static cudaStream_t sB = nullptr;
    static cudaEvent_t evFork = nullptr, evJoin = nullptr;
    static bool attrSet = false;
    if (sB == nullptr) {
        cudaStreamCreateWithFlags(&sB, cudaStreamNonBlocking);
        cudaEventCreateWithFlags(&evFork, cudaEventDisableTiming);
        cudaEventCreateWithFlags(&evJoin, cudaEventDisableTiming);
    }
    if (!attrSet) {
        cudaFuncSetAttribute(gemm_h_hmma,
                             cudaFuncAttributeMaxDynamicSharedMemorySize,
                             K1_SMEM_TOTAL);
        attrSet = true;
    }

    if (sB != nullptr) {
        cudaEventRecord(evFork, 0);
        cudaStreamWaitEvent(sB, evFork, 0);

        zero_cnt<<<(N / 4 + 255) / 256 + 1, 256, 0, sB>>>(N);
        hist_kernel<<<(E / 4 + 255) / 256 + 1, 256, 0, sB>>>(ei, E);
        scan_fused<<<nb, 256, 0, sB>>>(N, E, nb);
        scatter_kernel<<<(E / 4 + 255) / 256 + 1, 256, 0, sB>>>(ei, E);
        cudaEventRecord(evJoin, sB);

        gemm_h_hmma<<<(N + 127) / 128, 256, K1_SMEM_TOTAL>>>(x, Wlin, att, N);

        cudaStreamWaitEvent(0, evJoin, 0);
    } else {
        zero_cnt<<<(N / 4 + 255) / 256 + 1, 256>>>(N);
        gemm_h_hmma<<<(N + 127) / 128, 256, K1_SMEM_TOTAL>>>(x, Wlin, att, N);
        hist_kernel<<<(E / 4 + 255) / 256 + 1, 256>>>(ei, E);
        scan_fused<<<nb, 256>>>(N, E, nb);
        scatter_kernel<<<(E / 4 + 255) / 256 + 1, 256>>>(ei, E);
    }

    agg_kernel<<<(N * 32 + 255) / 256, 256>>>(N);
    gemm_out_hmma<<<(N + 127) / 128, 256>>>(Wout, bout, out, N);
}